// round 2
// baseline (speedup 1.0000x reference)
#include <cuda_runtime.h>
#include <cstddef>

#define VERY_NEG -1e30f
#define B_   128
#define S_   256
#define H_   256
#define C_   20000
#define A_   8
#define BS_  (B_*S_)      // 32768
#define CA_  (C_*A_)      // 160000

// ---------------- scratch (static device arrays; no allocation allowed) ----------------
__device__ float g_h1[CA_*H_];        // DAG MLP hidden: 160000 x 256 (163.8 MB)
__device__ float g_dict[(C_+1)*H_];   // dict_matrix: 20001 x 256
__device__ float g_xv[BS_*H_];        // visit stream x
__device__ float g_xd[BS_*H_];        // dag stream x
__device__ float g_t1[BS_*H_];        // x1 (post-attention residual)
__device__ float g_q[BS_*H_];
__device__ float g_k[BS_*H_];
__device__ float g_v[BS_*H_];
__device__ float g_ctx[BS_*H_];
__device__ float g_ff[BS_*4*H_];      // FFN hidden: 32768 x 1024 (134 MB)

// ---------------- generic tiled SGEMM: C = op(A[MxK] @ B[KxN] (+bias)(+res)) ----------------
// BM=BN=64, BK=16, 256 threads, 4x4 per thread.
__global__ __launch_bounds__(256) void sgemm_kernel(
    const float* __restrict__ A, const float* __restrict__ B,
    const float* __restrict__ bias, const float* __restrict__ res,
    float* __restrict__ C, int M, int N, int K, int do_relu)
{
    __shared__ float As[16][64];
    __shared__ float Bs[16][64];
    int bm = blockIdx.y, bn = blockIdx.x;
    int tid = threadIdx.x;
    int tx = tid & 15, ty = tid >> 4;
    int arow = tid >> 2, acol4 = (tid & 3) << 2;   // A: 64 rows x 4 float4s along K
    int brow = tid >> 4, bcol4 = (tid & 15) << 2;  // B: 16 rows x 16 float4s along N
    const float* Ablk = A + (size_t)bm * 64 * K;
    const float* Bblk = B + (size_t)bn * 64;
    float acc[4][4] = {};
    for (int k0 = 0; k0 < K; k0 += 16) {
        float4 av = *(const float4*)(Ablk + (size_t)arow * K + k0 + acol4);
        As[acol4+0][arow] = av.x; As[acol4+1][arow] = av.y;
        As[acol4+2][arow] = av.z; As[acol4+3][arow] = av.w;
        float4 bv = *(const float4*)(Bblk + (size_t)(k0 + brow) * N + bcol4);
        *(float4*)&Bs[brow][bcol4] = bv;
        __syncthreads();
        #pragma unroll
        for (int kk = 0; kk < 16; kk++) {
            float a[4], b[4];
            *(float4*)a = *(const float4*)&As[kk][ty * 4];
            *(float4*)b = *(const float4*)&Bs[kk][tx * 4];
            #pragma unroll
            for (int i = 0; i < 4; i++)
                #pragma unroll
                for (int j = 0; j < 4; j++)
                    acc[i][j] += a[i] * b[j];
        }
        __syncthreads();
    }
    int row0 = bm * 64 + ty * 4;
    int col0 = bn * 64 + tx * 4;
    #pragma unroll
    for (int i = 0; i < 4; i++) {
        float r[4];
        #pragma unroll
        for (int j = 0; j < 4; j++) {
            float v = acc[i][j];
            if (bias) v += bias[col0 + j];
            if (res)  v += res[(size_t)(row0 + i) * N + col0 + j];
            if (do_relu) v = fmaxf(v, 0.f);
            r[j] = v;
        }
        *(float4*)&C[(size_t)(row0 + i) * N + col0] = make_float4(r[0], r[1], r[2], r[3]);
    }
}

// ---------------- DAG MLP: gathered-A GEMM, A = concat(leaves*m, ancestors*m) ----------------
// M = C*A = 160000, K = 512, N = 256.  out = relu(A @ w1 + b1)
__global__ __launch_bounds__(256) void dag_mlp_kernel(
    const float* __restrict__ E,        // embed_init_w [NODES+1, 256]
    const int* __restrict__ leaves, const int* __restrict__ anc,
    const float* __restrict__ dmask,
    const float* __restrict__ w1, const float* __restrict__ b1,
    float* __restrict__ out)
{
    __shared__ float As[16][64];
    __shared__ float Bs[16][64];
    int bm = blockIdx.y, bn = blockIdx.x;
    int tid = threadIdx.x;
    int tx = tid & 15, ty = tid >> 4;
    int arow = tid >> 2, acol4 = (tid & 3) << 2;
    int brow = tid >> 4, bcol4 = (tid & 15) << 2;
    int m = bm * 64 + arow;
    int nl = leaves[m];
    int na = anc[m];
    float mm = dmask[m];
    const float* Bblk = w1 + (size_t)bn * 64;
    float acc[4][4] = {};
    for (int k0 = 0; k0 < 512; k0 += 16) {
        int k = k0 + acol4;
        const float* src = (k < 256) ? (E + (size_t)nl * 256 + k)
                                     : (E + (size_t)na * 256 + (k - 256));
        float4 av = *(const float4*)src;
        As[acol4+0][arow] = av.x * mm; As[acol4+1][arow] = av.y * mm;
        As[acol4+2][arow] = av.z * mm; As[acol4+3][arow] = av.w * mm;
        float4 bv = *(const float4*)(Bblk + (size_t)(k0 + brow) * 256 + bcol4);
        *(float4*)&Bs[brow][bcol4] = bv;
        __syncthreads();
        #pragma unroll
        for (int kk = 0; kk < 16; kk++) {
            float a[4], b[4];
            *(float4*)a = *(const float4*)&As[kk][ty * 4];
            *(float4*)b = *(const float4*)&Bs[kk][tx * 4];
            #pragma unroll
            for (int i = 0; i < 4; i++)
                #pragma unroll
                for (int j = 0; j < 4; j++)
                    acc[i][j] += a[i] * b[j];
        }
        __syncthreads();
    }
    int row0 = bm * 64 + ty * 4;
    int col0 = bn * 64 + tx * 4;
    #pragma unroll
    for (int i = 0; i < 4; i++) {
        float r[4];
        #pragma unroll
        for (int j = 0; j < 4; j++)
            r[j] = fmaxf(acc[i][j] + b1[col0 + j], 0.f);
        *(float4*)&out[(size_t)(row0 + i) * 256 + col0] = make_float4(r[0], r[1], r[2], r[3]);
    }
}

// ---------------- DAG reduce: per-code score/softmax/weighted-sum -> dict rows 1..C ----------------
__global__ __launch_bounds__(256) void dag_reduce_kernel(
    const float* __restrict__ h1, const float* __restrict__ w2, const float* __restrict__ b2,
    const int* __restrict__ anc, const float* __restrict__ dmask,
    const float* __restrict__ E, float* __restrict__ dict)
{
    int warp = threadIdx.x >> 5, lane = threadIdx.x & 31;
    if (blockIdx.x == 0) dict[threadIdx.x] = 0.f;    // zero dict row 0 (256 floats)
    int c = blockIdx.x * 8 + warp;
    if (c >= C_) return;
    float p[8];
    float esum = 0.f;
    #pragma unroll
    for (int a = 0; a < 8; a++) {
        const float* hr = h1 + (size_t)(c * 8 + a) * 256;
        float s = 0.f;
        for (int t = lane; t < 256; t += 32) s += hr[t] * w2[t];
        #pragma unroll
        for (int o = 16; o; o >>= 1) s += __shfl_xor_sync(0xffffffffu, s, o);
        float mk = dmask[c * 8 + a];
        s = s + b2[0] + (1.f - mk) * VERY_NEG;
        float e = __expf(s);            // scores are tiny; masked -> exp(-1e30)=0
        esum += e;
        p[a] = e * mk;
    }
    float inv = 1.f / esum;
    int nodes[8];
    #pragma unroll
    for (int a = 0; a < 8; a++) nodes[a] = anc[c * 8 + a];
    for (int t = lane; t < 256; t += 32) {
        float o = 0.f;
        #pragma unroll
        for (int a = 0; a < 8; a++) o += p[a] * E[(size_t)nodes[a] * 256 + t];
        dict[(size_t)(c + 1) * 256 + t] = o * inv;
    }
}

// ---------------- gather: inputs + inputs_dag ----------------
__global__ __launch_bounds__(256) void gather_kernel(
    const int* __restrict__ ids, const float* __restrict__ Ein,
    const float* __restrict__ dict, float* __restrict__ xv, float* __restrict__ xd)
{
    int bs = blockIdx.x;
    int t = threadIdx.x;
    int id = ids[bs];
    size_t o = (size_t)bs * 256 + t;
    xv[o] = Ein[(size_t)id * 256 + t];
    xd[o] = dict[(size_t)id * 256 + t];
}

// ---------------- attention: one block per (b,h); K,V in smem; single-pass softmax ----------------
__global__ __launch_bounds__(256) void attn_kernel(
    const float* __restrict__ q, const float* __restrict__ k, const float* __restrict__ v,
    const float* __restrict__ code_mask, float* __restrict__ ctx)
{
    extern __shared__ float sm[];
    float* Ks = sm;                  // 256*32
    float* Vs = sm + 256 * 32;       // 256*32
    float* Ms = sm + 2 * 256 * 32;   // 256
    int bh = blockIdx.x;
    int b = bh >> 3, h = bh & 7;
    int tid = threadIdx.x;
    size_t base = ((size_t)b * 256) * 256 + h * 32;
    for (int idx = tid; idx < 256 * 8; idx += 256) {
        int j = idx >> 3, t4 = (idx & 7) << 2;
        *(float4*)&Ks[j * 32 + t4] = *(const float4*)(k + base + (size_t)j * 256 + t4);
        *(float4*)&Vs[j * 32 + t4] = *(const float4*)(v + base + (size_t)j * 256 + t4);
    }
    Ms[tid] = (1.f - code_mask[b * 256 + tid]) * VERY_NEG;
    __syncthreads();

    int i = tid;   // q row
    float qr[32];
    const float* qp = q + base + (size_t)i * 256;
    #pragma unroll
    for (int t = 0; t < 32; t += 4) {
        float4 v4 = *(const float4*)(qp + t);
        qr[t] = v4.x; qr[t+1] = v4.y; qr[t+2] = v4.z; qr[t+3] = v4.w;
    }
    float acc[32];
    #pragma unroll
    for (int t = 0; t < 32; t++) acc[t] = 0.f;
    float l = 0.f;
    const float scale = 0.17677669529663687f;  // 1/sqrt(32)
    for (int j = 0; j < 256; j++) {
        float s = 0.f;
        #pragma unroll
        for (int t = 0; t < 32; t++) s += qr[t] * Ks[j * 32 + t];
        s = s * scale + Ms[j];
        float e = __expf(s);
        l += e;
        #pragma unroll
        for (int t = 0; t < 32; t++) acc[t] += e * Vs[j * 32 + t];
    }
    float inv = 1.f / l;
    float* cp = ctx + base + (size_t)i * 256;
    #pragma unroll
    for (int t = 0; t < 32; t += 4)
        *(float4*)(cp + t) = make_float4(acc[t]*inv, acc[t+1]*inv, acc[t+2]*inv, acc[t+3]*inv);
}

// ---------------- attention pooling ----------------
__global__ __launch_bounds__(256) void pool_kernel(
    const float* __restrict__ x, const float* __restrict__ pw, const float* __restrict__ pb,
    const float* __restrict__ code_mask, float* __restrict__ out)
{
    __shared__ float sp[256], sq[256];
    int b = blockIdx.x;
    int j = threadIdx.x;
    const float* xr = x + ((size_t)b * 256 + j) * 256;
    float s = 0.f;
    for (int t = 0; t < 256; t++) s += xr[t] * pw[t];
    s += pb[0] + (1.f - code_mask[b * 256 + j]) * VERY_NEG;
    sq[j] = s;
    __syncthreads();
    for (int o = 128; o; o >>= 1) { if (j < o) sq[j] = fmaxf(sq[j], sq[j + o]); __syncthreads(); }
    float mx = sq[0];
    __syncthreads();
    float e = __expf(s - mx);
    sp[j] = e; sq[j] = e;
    __syncthreads();
    for (int o = 128; o; o >>= 1) { if (j < o) sq[j] += sq[j + o]; __syncthreads(); }
    float inv = 1.f / sq[0];
    __syncthreads();
    float o = 0.f;
    for (int t = 0; t < 256; t++) o += sp[t] * x[((size_t)b * 256 + t) * 256 + j];
    out[(size_t)b * 256 + j] = o * inv;
}

// ---------------- launch ----------------
extern "C" void kernel_launch(void* const* d_in, const int* in_sizes, int n_in,
                              void* d_out, int out_size)
{
    const int*   input_ids = (const int*)  d_in[0];
    const float* code_mask = (const float*)d_in[1];
    const int*   leaves    = (const int*)  d_in[2];
    const int*   anc       = (const int*)  d_in[3];
    const float* dmask     = (const float*)d_in[4];
    const float* Einit     = (const float*)d_in[5];
    const float* Einp      = (const float*)d_in[6];
    const float* aw1       = (const float*)d_in[7];
    const float* ab1       = (const float*)d_in[8];
    const float* aw2       = (const float*)d_in[9];
    const float* ab2       = (const float*)d_in[10];
    const float* pw        = (const float*)d_in[11];
    const float* pb        = (const float*)d_in[12];
    float* out = (float*)d_out;

    float *h1, *dict, *xv, *xd, *t1, *q, *k, *v, *ctx, *ff;
    cudaGetSymbolAddress((void**)&h1,   g_h1);
    cudaGetSymbolAddress((void**)&dict, g_dict);
    cudaGetSymbolAddress((void**)&xv,   g_xv);
    cudaGetSymbolAddress((void**)&xd,   g_xd);
    cudaGetSymbolAddress((void**)&t1,   g_t1);
    cudaGetSymbolAddress((void**)&q,    g_q);
    cudaGetSymbolAddress((void**)&k,    g_k);
    cudaGetSymbolAddress((void**)&v,    g_v);
    cudaGetSymbolAddress((void**)&ctx,  g_ctx);
    cudaGetSymbolAddress((void**)&ff,   g_ff);

    int smem_bytes = (2 * 256 * 32 + 256) * 4;  // 66 KB
    cudaFuncSetAttribute(attn_kernel, cudaFuncAttributeMaxDynamicSharedMemorySize, smem_bytes);

    // ---- DAG embedding pipeline ----
    dag_mlp_kernel<<<dim3(4, CA_/64), 256>>>(Einit, leaves, anc, dmask, aw1, ab1, h1);
    dag_reduce_kernel<<<C_/8, 256>>>(h1, aw2, ab2, anc, dmask, Einit, dict);
    gather_kernel<<<BS_, 256>>>(input_ids, Einp, dict, xv, xd);

    // ---- two encoder layers ----
    auto encoder = [&](const float* X, int wb, float* O) {
        const float* wq  = (const float*)d_in[wb + 0];
        const float* wk  = (const float*)d_in[wb + 1];
        const float* wv  = (const float*)d_in[wb + 2];
        const float* wo  = (const float*)d_in[wb + 3];
        const float* fw1 = (const float*)d_in[wb + 4];
        const float* fb1 = (const float*)d_in[wb + 5];
        const float* fw2 = (const float*)d_in[wb + 6];
        const float* fb2 = (const float*)d_in[wb + 7];
        dim3 gH(H_/64, BS_/64);       // N=256
        dim3 gF(4*H_/64, BS_/64);     // N=1024
        sgemm_kernel<<<gH, 256>>>(X,   wq,  nullptr, nullptr, q,   BS_, H_,   H_,   0);
        sgemm_kernel<<<gH, 256>>>(X,   wk,  nullptr, nullptr, k,   BS_, H_,   H_,   0);
        sgemm_kernel<<<gH, 256>>>(X,   wv,  nullptr, nullptr, v,   BS_, H_,   H_,   0);
        attn_kernel<<<B_ * 8, 256, smem_bytes>>>(q, k, v, code_mask, ctx);
        sgemm_kernel<<<gH, 256>>>(ctx, wo,  nullptr, X,       t1,  BS_, H_,   H_,   0);  // x1 = x + ctx@wo
        sgemm_kernel<<<gF, 256>>>(t1,  fw1, fb1,     nullptr, ff,  BS_, 4*H_, H_,   1);  // relu(x1@fw1+fb1)
        sgemm_kernel<<<gH, 256>>>(ff,  fw2, fb2,     t1,      O,   BS_, H_,   4*H_, 0);  // x1 + h@fw2 + fb2
    };
    encoder(xv, 13, out);           // visit -> d_out[0 : 32768*256]
    encoder(xd, 21, xv);            // dag   -> reuse xv as output buffer

    // ---- pooling (dag stream) ----
    pool_kernel<<<B_, 256>>>(xv, pw, pb, code_mask, out + (size_t)BS_ * H_);
}

// round 4
// speedup vs baseline: 2.3734x; 2.3734x over previous
#include <cuda_runtime.h>
#include <cstdint>
#include <cstddef>

#define VERY_NEG -1e30f
#define B_   128
#define S_   256
#define H_   256
#define C_   20000
#define A_   8
#define BS_  (B_*S_)      // 32768
#define CA_  (C_*A_)      // 160000

// ================= scratch =================
__device__ float g_h1[CA_*H_];
__device__ float g_dict[(C_+1)*H_];
__device__ float g_xv[BS_*H_];
__device__ float g_xd[BS_*H_];
__device__ float g_t1[BS_*H_];
__device__ float g_q[BS_*H_];
__device__ float g_k[BS_*H_];
__device__ float g_v[BS_*H_];
__device__ float g_ctx[BS_*H_];
__device__ float g_ff[BS_*4*H_];
__device__ float g_wT[1703936 + 256];

// ================= tf32 warp MMA =================
__device__ __forceinline__ void mma_tf32(float* d, const uint32_t* a, const uint32_t* b)
{
    asm volatile(
        "mma.sync.aligned.m16n8k8.row.col.f32.tf32.tf32.f32 "
        "{%0,%1,%2,%3}, {%4,%5,%6,%7}, {%8,%9}, {%0,%1,%2,%3};\n"
        : "+f"(d[0]), "+f"(d[1]), "+f"(d[2]), "+f"(d[3])
        : "r"(a[0]), "r"(a[1]), "r"(a[2]), "r"(a[3]), "r"(b[0]), "r"(b[1]));
}

__device__ __forceinline__ uint32_t f2tf(float f)
{
    uint32_t u;
    asm("cvt.rna.tf32.f32 %0, %1;" : "=r"(u) : "f"(f));
    return u;
}
__device__ __forceinline__ uint4 cvt4(float4 v)
{
    uint4 o;
    o.x = f2tf(v.x); o.y = f2tf(v.y); o.z = f2tf(v.z); o.w = f2tf(v.w);
    return o;
}

#define SMSTRIDE 36
#define SM_TILE  (128 * SMSTRIDE)          // floats per tile
#define SM_TOTAL (4 * SM_TILE * 4)         // bytes: 2 bufs x (A+B)

// one 128x128x32 block-step of MMAs from smem buffers
__device__ __forceinline__ void mma_block(const float* sA, const float* sB,
                                          int wm, int wn, int lane, float acc[4][4][4])
{
    int tg = lane & 3, gp = lane >> 2;
    #pragma unroll
    for (int ks = 0; ks < 4; ks++) {
        int kb = ks * 8 + tg;
        uint32_t a[4][4], b[4][2];
        #pragma unroll
        for (int mi = 0; mi < 4; mi++) {
            int row = wm * 64 + mi * 16 + gp;
            a[mi][0] = __float_as_uint(sA[row * SMSTRIDE + kb]);
            a[mi][1] = __float_as_uint(sA[(row + 8) * SMSTRIDE + kb]);
            a[mi][2] = __float_as_uint(sA[row * SMSTRIDE + kb + 4]);
            a[mi][3] = __float_as_uint(sA[(row + 8) * SMSTRIDE + kb + 4]);
        }
        #pragma unroll
        for (int ni = 0; ni < 4; ni++) {
            int nr = wn * 32 + ni * 8 + gp;
            b[ni][0] = __float_as_uint(sB[nr * SMSTRIDE + kb]);
            b[ni][1] = __float_as_uint(sB[nr * SMSTRIDE + kb + 4]);
        }
        #pragma unroll
        for (int mi = 0; mi < 4; mi++)
            #pragma unroll
            for (int ni = 0; ni < 4; ni++)
                mma_tf32(acc[mi][ni], a[mi], b[ni]);
    }
}

// ================= dense tf32 GEMM: C[M,N] = op(A[M,K] @ Bt[N,K]^T) =================
__global__ __launch_bounds__(256) void tf32_gemm(
    const float* __restrict__ A, const float* __restrict__ Bt,
    const float* __restrict__ bias, const float* __restrict__ res,
    float* __restrict__ C, int M, int N, int K, int do_relu)
{
    extern __shared__ float sm[];
    int tid = threadIdx.x;
    int bm = blockIdx.x, bn = blockIdx.y;
    int lane = tid & 31, wid = tid >> 5;
    int wm = wid >> 2, wn = wid & 3;
    int r0 = tid >> 3, c4 = tid & 7;

    const float* Ab = A + (size_t)(bm * 128 + r0) * K + c4 * 4;
    const float* Bb = Bt + (size_t)(bn * 128 + r0) * K + c4 * 4;
    float acc[4][4][4];
    #pragma unroll
    for (int i = 0; i < 4; i++)
        #pragma unroll
        for (int j = 0; j < 4; j++)
            #pragma unroll
            for (int t = 0; t < 4; t++) acc[i][j][t] = 0.f;

    int NC = K >> 5;
    float4 ra[4], rb[4];
    // prologue: tile 0
    #pragma unroll
    for (int i = 0; i < 4; i++) {
        ra[i] = *(const float4*)(Ab + (size_t)i * 32 * K);
        rb[i] = *(const float4*)(Bb + (size_t)i * 32 * K);
    }
    #pragma unroll
    for (int i = 0; i < 4; i++) {
        *(uint4*)&sm[(r0 + i * 32) * SMSTRIDE + c4 * 4] = cvt4(ra[i]);
        *(uint4*)&sm[SM_TILE + (r0 + i * 32) * SMSTRIDE + c4 * 4] = cvt4(rb[i]);
    }
    __syncthreads();

    for (int kc = 0; kc < NC; kc++) {
        int buf = kc & 1;
        if (kc + 1 < NC) {
            int k0 = (kc + 1) << 5;
            #pragma unroll
            for (int i = 0; i < 4; i++) {
                ra[i] = *(const float4*)(Ab + (size_t)i * 32 * K + k0);
                rb[i] = *(const float4*)(Bb + (size_t)i * 32 * K + k0);
            }
        }
        mma_block(sm + buf * 2 * SM_TILE, sm + buf * 2 * SM_TILE + SM_TILE, wm, wn, lane, acc);
        if (kc + 1 < NC) {
            int nb = buf ^ 1;
            #pragma unroll
            for (int i = 0; i < 4; i++) {
                *(uint4*)&sm[nb * 2 * SM_TILE + (r0 + i * 32) * SMSTRIDE + c4 * 4] = cvt4(ra[i]);
                *(uint4*)&sm[nb * 2 * SM_TILE + SM_TILE + (r0 + i * 32) * SMSTRIDE + c4 * 4] = cvt4(rb[i]);
            }
            __syncthreads();
        }
    }

    // epilogue
    int tg = lane & 3, gp = lane >> 2;
    #pragma unroll
    for (int mi = 0; mi < 4; mi++) {
        #pragma unroll
        for (int ni = 0; ni < 4; ni++) {
            int rl = wm * 64 + mi * 16 + gp;
            int col = bn * 128 + wn * 32 + ni * 8 + tg * 2;
            float2 bv = make_float2(0.f, 0.f);
            if (bias) bv = *(const float2*)(bias + col);
            #pragma unroll
            for (int h = 0; h < 2; h++) {
                size_t rowg = (size_t)bm * 128 + rl + h * 8;
                float2 v = make_float2(acc[mi][ni][2 * h] + bv.x, acc[mi][ni][2 * h + 1] + bv.y);
                if (res) {
                    float2 rv = *(const float2*)(res + rowg * N + col);
                    v.x += rv.x; v.y += rv.y;
                }
                if (do_relu) { v.x = fmaxf(v.x, 0.f); v.y = fmaxf(v.y, 0.f); }
                *(float2*)(C + rowg * N + col) = v;
            }
        }
    }
}

// ================= DAG MLP: h1 = relu(mk * (concat(E[l],E[a]) @ w1T^T) + b1) =================
__global__ __launch_bounds__(256) void tf32_dag_mlp(
    const float* __restrict__ E, const int* __restrict__ leaves, const int* __restrict__ anc,
    const float* __restrict__ dmask, const float* __restrict__ w1T,
    const float* __restrict__ b1, float* __restrict__ out)
{
    extern __shared__ float sm[];
    int tid = threadIdx.x;
    int bm = blockIdx.x, bn = blockIdx.y;
    int lane = tid & 31, wid = tid >> 5;
    int wm = wid >> 2, wn = wid & 3;
    int r0 = tid >> 3, c4 = tid & 7;

    int nl[4], na[4];
    #pragma unroll
    for (int i = 0; i < 4; i++) {
        int m = bm * 128 + r0 + i * 32;
        nl[i] = leaves[m]; na[i] = anc[m];
    }
    const float* Bb = w1T + (size_t)(bn * 128 + r0) * 512 + c4 * 4;
    float acc[4][4][4];
    #pragma unroll
    for (int i = 0; i < 4; i++)
        #pragma unroll
        for (int j = 0; j < 4; j++)
            #pragma unroll
            for (int t = 0; t < 4; t++) acc[i][j][t] = 0.f;

    const int NC = 16;  // K = 512
    float4 ra[4], rb[4];
    #pragma unroll
    for (int i = 0; i < 4; i++) {
        ra[i] = *(const float4*)(E + (size_t)nl[i] * 256 + c4 * 4);
        rb[i] = *(const float4*)(Bb + (size_t)i * 32 * 512);
    }
    #pragma unroll
    for (int i = 0; i < 4; i++) {
        *(uint4*)&sm[(r0 + i * 32) * SMSTRIDE + c4 * 4] = cvt4(ra[i]);
        *(uint4*)&sm[SM_TILE + (r0 + i * 32) * SMSTRIDE + c4 * 4] = cvt4(rb[i]);
    }
    __syncthreads();

    for (int kc = 0; kc < NC; kc++) {
        int buf = kc & 1;
        if (kc + 1 < NC) {
            int k0 = (kc + 1) << 5;
            int kk = k0 & 255;
            bool first = k0 < 256;
            #pragma unroll
            for (int i = 0; i < 4; i++) {
                int node = first ? nl[i] : na[i];
                ra[i] = *(const float4*)(E + (size_t)node * 256 + kk + c4 * 4);
                rb[i] = *(const float4*)(Bb + (size_t)i * 32 * 512 + k0);
            }
        }
        mma_block(sm + buf * 2 * SM_TILE, sm + buf * 2 * SM_TILE + SM_TILE, wm, wn, lane, acc);
        if (kc + 1 < NC) {
            int nb = buf ^ 1;
            #pragma unroll
            for (int i = 0; i < 4; i++) {
                *(uint4*)&sm[nb * 2 * SM_TILE + (r0 + i * 32) * SMSTRIDE + c4 * 4] = cvt4(ra[i]);
                *(uint4*)&sm[nb * 2 * SM_TILE + SM_TILE + (r0 + i * 32) * SMSTRIDE + c4 * 4] = cvt4(rb[i]);
            }
            __syncthreads();
        }
    }

    int tg = lane & 3, gp = lane >> 2;
    #pragma unroll
    for (int mi = 0; mi < 4; mi++) {
        int rl = wm * 64 + mi * 16 + gp;
        float mk0 = dmask[bm * 128 + rl];
        float mk1 = dmask[bm * 128 + rl + 8];
        #pragma unroll
        for (int ni = 0; ni < 4; ni++) {
            int col = bn * 128 + wn * 32 + ni * 8 + tg * 2;
            float2 bv = *(const float2*)(b1 + col);
            float2 v0 = make_float2(fmaxf(mk0 * acc[mi][ni][0] + bv.x, 0.f),
                                    fmaxf(mk0 * acc[mi][ni][1] + bv.y, 0.f));
            float2 v1 = make_float2(fmaxf(mk1 * acc[mi][ni][2] + bv.x, 0.f),
                                    fmaxf(mk1 * acc[mi][ni][3] + bv.y, 0.f));
            *(float2*)(out + ((size_t)bm * 128 + rl) * 256 + col) = v0;
            *(float2*)(out + ((size_t)bm * 128 + rl + 8) * 256 + col) = v1;
        }
    }
}

// ================= transpose =================
__global__ __launch_bounds__(256) void transpose_kernel(
    const float* __restrict__ in, float* __restrict__ out, int R, int Ccols)
{
    __shared__ float t[32][33];
    int x = threadIdx.x & 31, y0 = threadIdx.x >> 5;
    int c = blockIdx.x * 32 + x;
    #pragma unroll
    for (int i = 0; i < 32; i += 8)
        t[y0 + i][x] = in[(size_t)(blockIdx.y * 32 + y0 + i) * Ccols + c];
    __syncthreads();
    int rr = blockIdx.y * 32 + x;
    #pragma unroll
    for (int i = 0; i < 32; i += 8)
        out[(size_t)(blockIdx.x * 32 + y0 + i) * R + rr] = t[x][y0 + i];
}

// ================= DAG reduce =================
__global__ __launch_bounds__(256) void dag_reduce_kernel(
    const float* __restrict__ h1, const float* __restrict__ w2, const float* __restrict__ b2,
    const int* __restrict__ anc, const float* __restrict__ dmask,
    const float* __restrict__ E, float* __restrict__ dict)
{
    int warp = threadIdx.x >> 5, lane = threadIdx.x & 31;
    if (blockIdx.x == 0) dict[threadIdx.x] = 0.f;
    int c = blockIdx.x * 8 + warp;
    if (c >= C_) return;
    float p[8];
    float esum = 0.f;
    #pragma unroll
    for (int a = 0; a < 8; a++) {
        const float* hr = h1 + (size_t)(c * 8 + a) * 256;
        float s = 0.f;
        for (int t = lane; t < 256; t += 32) s += hr[t] * w2[t];
        #pragma unroll
        for (int o = 16; o; o >>= 1) s += __shfl_xor_sync(0xffffffffu, s, o);
        float mkk = dmask[c * 8 + a];
        s = s + b2[0] + (1.f - mkk) * VERY_NEG;
        float e = __expf(s);
        esum += e;
        p[a] = e * mkk;
    }
    float inv = 1.f / esum;
    int nodes[8];
    #pragma unroll
    for (int a = 0; a < 8; a++) nodes[a] = anc[c * 8 + a];
    for (int t = lane; t < 256; t += 32) {
        float o = 0.f;
        #pragma unroll
        for (int a = 0; a < 8; a++) o += p[a] * E[(size_t)nodes[a] * 256 + t];
        dict[(size_t)(c + 1) * 256 + t] = o * inv;
    }
}

// ================= gather =================
__global__ __launch_bounds__(256) void gather_kernel(
    const int* __restrict__ ids, const float* __restrict__ Ein,
    const float* __restrict__ dict, float* __restrict__ xv, float* __restrict__ xd)
{
    int bs = blockIdx.x;
    int t = threadIdx.x;
    int id = ids[bs];
    size_t o = (size_t)bs * 256 + t;
    xv[o] = Ein[(size_t)id * 256 + t];
    xd[o] = dict[(size_t)id * 256 + t];
}

// ================= attention =================
__global__ __launch_bounds__(256) void attn_kernel(
    const float* __restrict__ q, const float* __restrict__ k, const float* __restrict__ v,
    const float* __restrict__ code_mask, float* __restrict__ ctx)
{
    extern __shared__ float smf[];
    float* Ks = smf;
    float* Vs = smf + 256 * 32;
    float* Ms = smf + 2 * 256 * 32;
    int bh = blockIdx.x;
    int b = bh >> 3, h = bh & 7;
    int tid = threadIdx.x;
    size_t base = ((size_t)b * 256) * 256 + h * 32;
    for (int idx = tid; idx < 256 * 8; idx += 256) {
        int j = idx >> 3, t4 = (idx & 7) << 2;
        *(float4*)&Ks[j * 32 + t4] = *(const float4*)(k + base + (size_t)j * 256 + t4);
        *(float4*)&Vs[j * 32 + t4] = *(const float4*)(v + base + (size_t)j * 256 + t4);
    }
    Ms[tid] = (1.f - code_mask[b * 256 + tid]) * VERY_NEG;
    __syncthreads();

    int i = tid;
    float qr[32];
    const float* qp = q + base + (size_t)i * 256;
    #pragma unroll
    for (int t = 0; t < 32; t += 4) {
        float4 v4 = *(const float4*)(qp + t);
        qr[t] = v4.x; qr[t+1] = v4.y; qr[t+2] = v4.z; qr[t+3] = v4.w;
    }
    float acc[32];
    #pragma unroll
    for (int t = 0; t < 32; t++) acc[t] = 0.f;
    float l = 0.f;
    const float scale = 0.17677669529663687f;
    for (int j = 0; j < 256; j++) {
        float s = 0.f;
        #pragma unroll
        for (int t = 0; t < 32; t++) s += qr[t] * Ks[j * 32 + t];
        s = s * scale + Ms[j];
        float e = __expf(s);
        l += e;
        #pragma unroll
        for (int t = 0; t < 32; t++) acc[t] += e * Vs[j * 32 + t];
    }
    float inv = 1.f / l;
    float* cp = ctx + base + (size_t)i * 256;
    #pragma unroll
    for (int t = 0; t < 32; t += 4)
        *(float4*)(cp + t) = make_float4(acc[t]*inv, acc[t+1]*inv, acc[t+2]*inv, acc[t+3]*inv);
}

// ================= pooling =================
__global__ __launch_bounds__(256) void pool_kernel(
    const float* __restrict__ x, const float* __restrict__ pw, const float* __restrict__ pb,
    const float* __restrict__ code_mask, float* __restrict__ out)
{
    __shared__ float sp[256], sq[256];
    int b = blockIdx.x;
    int j = threadIdx.x;
    const float* xr = x + ((size_t)b * 256 + j) * 256;
    float s = 0.f;
    for (int t = 0; t < 256; t++) s += xr[t] * pw[t];
    s += pb[0] + (1.f - code_mask[b * 256 + j]) * VERY_NEG;
    sq[j] = s;
    __syncthreads();
    for (int o = 128; o; o >>= 1) { if (j < o) sq[j] = fmaxf(sq[j], sq[j + o]); __syncthreads(); }
    float mx = sq[0];
    __syncthreads();
    float e = __expf(s - mx);
    sp[j] = e; sq[j] = e;
    __syncthreads();
    for (int o = 128; o; o >>= 1) { if (j < o) sq[j] += sq[j + o]; __syncthreads(); }
    float inv = 1.f / sq[0];
    __syncthreads();
    float o = 0.f;
    for (int t = 0; t < 256; t++) o += sp[t] * x[((size_t)b * 256 + t) * 256 + j];
    out[(size_t)b * 256 + j] = o * inv;
}

// ================= launch =================
extern "C" void kernel_launch(void* const* d_in, const int* in_sizes, int n_in,
                              void* d_out, int out_size)
{
    const int*   input_ids = (const int*)  d_in[0];
    const float* code_mask = (const float*)d_in[1];
    const int*   leaves    = (const int*)  d_in[2];
    const int*   anc       = (const int*)  d_in[3];
    const float* dmask     = (const float*)d_in[4];
    const float* Einit     = (const float*)d_in[5];
    const float* Einp      = (const float*)d_in[6];
    const float* aw1       = (const float*)d_in[7];
    const float* ab1       = (const float*)d_in[8];
    const float* aw2       = (const float*)d_in[9];
    const float* ab2       = (const float*)d_in[10];
    const float* pw        = (const float*)d_in[11];
    const float* pb        = (const float*)d_in[12];
    float* out = (float*)d_out;

    float *h1, *dict, *xv, *xd, *t1, *q, *k, *v, *ctx, *ff, *wT;
    cudaGetSymbolAddress((void**)&h1,   g_h1);
    cudaGetSymbolAddress((void**)&dict, g_dict);
    cudaGetSymbolAddress((void**)&xv,   g_xv);
    cudaGetSymbolAddress((void**)&xd,   g_xd);
    cudaGetSymbolAddress((void**)&t1,   g_t1);
    cudaGetSymbolAddress((void**)&q,    g_q);
    cudaGetSymbolAddress((void**)&k,    g_k);
    cudaGetSymbolAddress((void**)&v,    g_v);
    cudaGetSymbolAddress((void**)&ctx,  g_ctx);
    cudaGetSymbolAddress((void**)&ff,   g_ff);
    cudaGetSymbolAddress((void**)&wT,   g_wT);

    cudaFuncSetAttribute(tf32_gemm,    cudaFuncAttributeMaxDynamicSharedMemorySize, SM_TOTAL);
    cudaFuncSetAttribute(tf32_dag_mlp, cudaFuncAttributeMaxDynamicSharedMemorySize, SM_TOTAL);
    int attn_smem = (2 * 256 * 32 + 256) * 4;
    cudaFuncSetAttribute(attn_kernel, cudaFuncAttributeMaxDynamicSharedMemorySize, attn_smem);

    // ---- weight transposes into scratch ----
    auto T = [&](const float* w, float* o, int R, int Cc) {
        transpose_kernel<<<dim3(Cc / 32, R / 32), 256>>>(w, o, R, Cc);
    };
    T(aw1, wT + 1572864, 512, 256);
    for (int l = 0; l < 2; l++) {
        int wb = 13 + 8 * l;
        float* base = wT + l * 786432;
        T((const float*)d_in[wb + 0], base + 0,      256, 256);   // wq
        T((const float*)d_in[wb + 1], base + 65536,  256, 256);   // wk
        T((const float*)d_in[wb + 2], base + 131072, 256, 256);   // wv
        T((const float*)d_in[wb + 3], base + 196608, 256, 256);   // wo
        T((const float*)d_in[wb + 4], base + 262144, 256, 1024);  // fw1 -> [1024,256]
        T((const float*)d_in[wb + 6], base + 524288, 1024, 256);  // fw2 -> [256,1024]
    }

    // ---- DAG embedding pipeline ----
    tf32_dag_mlp<<<dim3(CA_ / 128, 2), 256, SM_TOTAL>>>(Einit, leaves, anc, dmask,
                                                        wT + 1572864, ab1, h1);
    dag_reduce_kernel<<<C_ / 8, 256>>>(h1, aw2, ab2, anc, dmask, Einit, dict);
    gather_kernel<<<BS_, 256>>>(input_ids, Einp, dict, xv, xd);

    // ---- two encoder layers ----
    auto encoder = [&](const float* X, int l, float* O) {
        float* base = wT + l * 786432;
        const float* fb1 = (const float*)d_in[13 + 8 * l + 5];
        const float* fb2 = (const float*)d_in[13 + 8 * l + 7];
        dim3 gH(BS_ / 128, 2);
        dim3 gF(BS_ / 128, 8);
        tf32_gemm<<<gH, 256, SM_TOTAL>>>(X,   base + 0,      nullptr, nullptr, q,  BS_, 256,  256,  0);
        tf32_gemm<<<gH, 256, SM_TOTAL>>>(X,   base + 65536,  nullptr, nullptr, k,  BS_, 256,  256,  0);
        tf32_gemm<<<gH, 256, SM_TOTAL>>>(X,   base + 131072, nullptr, nullptr, v,  BS_, 256,  256,  0);
        attn_kernel<<<B_ * 8, 256, attn_smem>>>(q, k, v, code_mask, ctx);
        tf32_gemm<<<gH, 256, SM_TOTAL>>>(ctx, base + 196608, nullptr, X,       t1, BS_, 256,  256,  0);
        tf32_gemm<<<gF, 256, SM_TOTAL>>>(t1,  base + 262144, fb1,     nullptr, ff, BS_, 1024, 256,  1);
        tf32_gemm<<<gH, 256, SM_TOTAL>>>(ff,  base + 524288, fb2,     t1,      O,  BS_, 256,  1024, 0);
    };
    encoder(xv, 0, out);
    encoder(xd, 1, xv);

    pool_kernel<<<B_, 256>>>(xv, pw, pb, code_mask, out + (size_t)BS_ * H_);
}

// round 5
// speedup vs baseline: 3.3061x; 1.3930x over previous
#include <cuda_runtime.h>
#include <cstdint>
#include <cstddef>

#define VERY_NEG -1e30f
#define B_   128
#define S_   256
#define H_   256
#define C_   20000
#define A_   8
#define BS_  (B_*S_)      // 32768
#define CA_  (C_*A_)      // 160000

// ================= scratch =================
__device__ float g_dict[(C_+1)*H_];
__device__ float g_xv[BS_*H_];
__device__ float g_xd[BS_*H_];
__device__ float g_t1[BS_*H_];
__device__ float g_qkv[BS_*768];
__device__ float g_ctx[BS_*H_];
__device__ float g_ff[BS_*4*H_];
__device__ float g_wT[1703936 + 256];
__device__ float g_scores[CA_];

// ================= tf32 warp MMA =================
__device__ __forceinline__ void mma_tf32(float* d, const uint32_t* a, const uint32_t* b)
{
    asm volatile(
        "mma.sync.aligned.m16n8k8.row.col.f32.tf32.tf32.f32 "
        "{%0,%1,%2,%3}, {%4,%5,%6,%7}, {%8,%9}, {%0,%1,%2,%3};\n"
        : "+f"(d[0]), "+f"(d[1]), "+f"(d[2]), "+f"(d[3])
        : "r"(a[0]), "r"(a[1]), "r"(a[2]), "r"(a[3]), "r"(b[0]), "r"(b[1]));
}
__device__ __forceinline__ uint32_t f2tf(float f)
{
    uint32_t u;
    asm("cvt.rna.tf32.f32 %0, %1;" : "=r"(u) : "f"(f));
    return u;
}
__device__ __forceinline__ uint4 cvt4(float4 v)
{
    uint4 o;
    o.x = f2tf(v.x); o.y = f2tf(v.y); o.z = f2tf(v.z); o.w = f2tf(v.w);
    return o;
}

#define SMSTRIDE 36
#define SM_TILE  (128 * SMSTRIDE)
#define SM_TOTAL (4 * SM_TILE * 4)

// one 128x128x32 block-step of MMAs from smem buffers
__device__ __forceinline__ void mma_block(const float* sA, const float* sB,
                                          int wm, int wn, int lane, float acc[4][4][4])
{
    int tg = lane & 3, gp = lane >> 2;
    #pragma unroll
    for (int ks = 0; ks < 4; ks++) {
        int kb = ks * 8 + tg;
        uint32_t a[4][4], b[4][2];
        #pragma unroll
        for (int mi = 0; mi < 4; mi++) {
            int row = wm * 64 + mi * 16 + gp;
            a[mi][0] = __float_as_uint(sA[row * SMSTRIDE + kb]);
            a[mi][1] = __float_as_uint(sA[(row + 8) * SMSTRIDE + kb]);
            a[mi][2] = __float_as_uint(sA[row * SMSTRIDE + kb + 4]);
            a[mi][3] = __float_as_uint(sA[(row + 8) * SMSTRIDE + kb + 4]);
        }
        #pragma unroll
        for (int ni = 0; ni < 4; ni++) {
            int nr = wn * 32 + ni * 8 + gp;
            b[ni][0] = __float_as_uint(sB[nr * SMSTRIDE + kb]);
            b[ni][1] = __float_as_uint(sB[nr * SMSTRIDE + kb + 4]);
        }
        #pragma unroll
        for (int mi = 0; mi < 4; mi++)
            #pragma unroll
            for (int ni = 0; ni < 4; ni++)
                mma_tf32(acc[mi][ni], a[mi], b[ni]);
    }
}

// ================= dense tf32 GEMM: C[M,N] = op(A[M,K] @ Bt[N,K]^T) =================
__global__ __launch_bounds__(256) void tf32_gemm(
    const float* __restrict__ A, const float* __restrict__ Bt,
    const float* __restrict__ bias, const float* __restrict__ res,
    float* __restrict__ C, int M, int N, int K, int do_relu)
{
    extern __shared__ float sm[];
    int tid = threadIdx.x;
    int bm = blockIdx.x, bn = blockIdx.y;
    int lane = tid & 31, wid = tid >> 5;
    int wm = wid >> 2, wn = wid & 3;
    int r0 = tid >> 3, c4 = tid & 7;

    const float* Ab = A + (size_t)(bm * 128 + r0) * K + c4 * 4;
    const float* Bb = Bt + (size_t)(bn * 128 + r0) * K + c4 * 4;
    float acc[4][4][4];
    #pragma unroll
    for (int i = 0; i < 4; i++)
        #pragma unroll
        for (int j = 0; j < 4; j++)
            #pragma unroll
            for (int t = 0; t < 4; t++) acc[i][j][t] = 0.f;

    int NC = K >> 5;
    float4 ra[4], rb[4];
    #pragma unroll
    for (int i = 0; i < 4; i++) {
        ra[i] = *(const float4*)(Ab + (size_t)i * 32 * K);
        rb[i] = *(const float4*)(Bb + (size_t)i * 32 * K);
    }
    #pragma unroll
    for (int i = 0; i < 4; i++) {
        *(uint4*)&sm[(r0 + i * 32) * SMSTRIDE + c4 * 4] = cvt4(ra[i]);
        *(uint4*)&sm[SM_TILE + (r0 + i * 32) * SMSTRIDE + c4 * 4] = cvt4(rb[i]);
    }
    __syncthreads();

    for (int kc = 0; kc < NC; kc++) {
        int buf = kc & 1;
        if (kc + 1 < NC) {
            int k0 = (kc + 1) << 5;
            #pragma unroll
            for (int i = 0; i < 4; i++) {
                ra[i] = *(const float4*)(Ab + (size_t)i * 32 * K + k0);
                rb[i] = *(const float4*)(Bb + (size_t)i * 32 * K + k0);
            }
        }
        mma_block(sm + buf * 2 * SM_TILE, sm + buf * 2 * SM_TILE + SM_TILE, wm, wn, lane, acc);
        if (kc + 1 < NC) {
            int nb = buf ^ 1;
            #pragma unroll
            for (int i = 0; i < 4; i++) {
                *(uint4*)&sm[nb * 2 * SM_TILE + (r0 + i * 32) * SMSTRIDE + c4 * 4] = cvt4(ra[i]);
                *(uint4*)&sm[nb * 2 * SM_TILE + SM_TILE + (r0 + i * 32) * SMSTRIDE + c4 * 4] = cvt4(rb[i]);
            }
            __syncthreads();
        }
    }

    int tg = lane & 3, gp = lane >> 2;
    #pragma unroll
    for (int mi = 0; mi < 4; mi++) {
        #pragma unroll
        for (int ni = 0; ni < 4; ni++) {
            int rl = wm * 64 + mi * 16 + gp;
            int col = bn * 128 + wn * 32 + ni * 8 + tg * 2;
            float2 bv = make_float2(0.f, 0.f);
            if (bias) bv = *(const float2*)(bias + col);
            #pragma unroll
            for (int h = 0; h < 2; h++) {
                size_t rowg = (size_t)bm * 128 + rl + h * 8;
                float2 v = make_float2(acc[mi][ni][2 * h] + bv.x, acc[mi][ni][2 * h + 1] + bv.y);
                if (res) {
                    float2 rv = *(const float2*)(res + rowg * N + col);
                    v.x += rv.x; v.y += rv.y;
                }
                if (do_relu) { v.x = fmaxf(v.x, 0.f); v.y = fmaxf(v.y, 0.f); }
                *(float2*)(C + rowg * N + col) = v;
            }
        }
    }
}

// ================= DAG MLP fused: atomically accumulate relu(...)·w2 into scores =================
__global__ __launch_bounds__(256) void tf32_dag_mlp(
    const float* __restrict__ E, const int* __restrict__ leaves, const int* __restrict__ anc,
    const float* __restrict__ dmask, const float* __restrict__ w1T,
    const float* __restrict__ b1, const float* __restrict__ w2, float* __restrict__ scores)
{
    extern __shared__ float sm[];
    int tid = threadIdx.x;
    int bm = blockIdx.x, bn = blockIdx.y;
    int lane = tid & 31, wid = tid >> 5;
    int wm = wid >> 2, wn = wid & 3;
    int r0 = tid >> 3, c4 = tid & 7;

    int nl[4], na[4];
    #pragma unroll
    for (int i = 0; i < 4; i++) {
        int m = bm * 128 + r0 + i * 32;
        nl[i] = leaves[m]; na[i] = anc[m];
    }
    const float* Bb = w1T + (size_t)(bn * 128 + r0) * 512 + c4 * 4;
    float acc[4][4][4];
    #pragma unroll
    for (int i = 0; i < 4; i++)
        #pragma unroll
        for (int j = 0; j < 4; j++)
            #pragma unroll
            for (int t = 0; t < 4; t++) acc[i][j][t] = 0.f;

    const int NC = 16;
    float4 ra[4], rb[4];
    #pragma unroll
    for (int i = 0; i < 4; i++) {
        ra[i] = *(const float4*)(E + (size_t)nl[i] * 256 + c4 * 4);
        rb[i] = *(const float4*)(Bb + (size_t)i * 32 * 512);
    }
    #pragma unroll
    for (int i = 0; i < 4; i++) {
        *(uint4*)&sm[(r0 + i * 32) * SMSTRIDE + c4 * 4] = cvt4(ra[i]);
        *(uint4*)&sm[SM_TILE + (r0 + i * 32) * SMSTRIDE + c4 * 4] = cvt4(rb[i]);
    }
    __syncthreads();

    for (int kc = 0; kc < NC; kc++) {
        int buf = kc & 1;
        if (kc + 1 < NC) {
            int k0 = (kc + 1) << 5;
            int kk = k0 & 255;
            bool first = k0 < 256;
            #pragma unroll
            for (int i = 0; i < 4; i++) {
                int node = first ? nl[i] : na[i];
                ra[i] = *(const float4*)(E + (size_t)node * 256 + kk + c4 * 4);
                rb[i] = *(const float4*)(Bb + (size_t)i * 32 * 512 + k0);
            }
        }
        mma_block(sm + buf * 2 * SM_TILE, sm + buf * 2 * SM_TILE + SM_TILE, wm, wn, lane, acc);
        if (kc + 1 < NC) {
            int nb = buf ^ 1;
            #pragma unroll
            for (int i = 0; i < 4; i++) {
                *(uint4*)&sm[nb * 2 * SM_TILE + (r0 + i * 32) * SMSTRIDE + c4 * 4] = cvt4(ra[i]);
                *(uint4*)&sm[nb * 2 * SM_TILE + SM_TILE + (r0 + i * 32) * SMSTRIDE + c4 * 4] = cvt4(rb[i]);
            }
            __syncthreads();
        }
    }

    int tg = lane & 3, gp = lane >> 2;
    float2 bv[4], w2v[4];
    #pragma unroll
    for (int ni = 0; ni < 4; ni++) {
        int col = bn * 128 + wn * 32 + ni * 8 + tg * 2;
        bv[ni] = *(const float2*)(b1 + col);
        w2v[ni] = *(const float2*)(w2 + col);
    }
    #pragma unroll
    for (int mi = 0; mi < 4; mi++) {
        int rl = wm * 64 + mi * 16 + gp;
        float mk0 = dmask[bm * 128 + rl];
        float mk1 = dmask[bm * 128 + rl + 8];
        float p0 = 0.f, p1 = 0.f;
        #pragma unroll
        for (int ni = 0; ni < 4; ni++) {
            float v0x = fmaxf(mk0 * acc[mi][ni][0] + bv[ni].x, 0.f);
            float v0y = fmaxf(mk0 * acc[mi][ni][1] + bv[ni].y, 0.f);
            float v1x = fmaxf(mk1 * acc[mi][ni][2] + bv[ni].x, 0.f);
            float v1y = fmaxf(mk1 * acc[mi][ni][3] + bv[ni].y, 0.f);
            p0 += v0x * w2v[ni].x + v0y * w2v[ni].y;
            p1 += v1x * w2v[ni].x + v1y * w2v[ni].y;
        }
        p0 += __shfl_xor_sync(0xffffffffu, p0, 1);
        p0 += __shfl_xor_sync(0xffffffffu, p0, 2);
        p1 += __shfl_xor_sync(0xffffffffu, p1, 1);
        p1 += __shfl_xor_sync(0xffffffffu, p1, 2);
        if (tg == 0) {
            atomicAdd(scores + bm * 128 + rl, p0);
            atomicAdd(scores + bm * 128 + rl + 8, p1);
        }
    }
}

// ================= zero scores =================
__global__ __launch_bounds__(256) void zero_scores(float* s)
{
    int i = blockIdx.x * 256 + threadIdx.x;
    if (i < CA_) s[i] = 0.f;
}

// ================= batched transpose =================
struct TransDesc { const float* src; float* dst; int R, C; };
struct TransArgs { TransDesc d[13]; };
__global__ __launch_bounds__(256) void transpose_all(TransArgs args)
{
    TransDesc t = args.d[blockIdx.z];
    if (blockIdx.x * 32 >= t.C || blockIdx.y * 32 >= t.R) return;
    __shared__ float tt[32][33];
    int x = threadIdx.x & 31, y0 = threadIdx.x >> 5;
    int c = blockIdx.x * 32 + x;
    #pragma unroll
    for (int i = 0; i < 32; i += 8)
        tt[y0 + i][x] = t.src[(size_t)(blockIdx.y * 32 + y0 + i) * t.C + c];
    __syncthreads();
    int rr = blockIdx.y * 32 + x;
    #pragma unroll
    for (int i = 0; i < 32; i += 8)
        t.dst[(size_t)(blockIdx.x * 32 + y0 + i) * t.R + rr] = tt[x][y0 + i];
}

// ================= DAG reduce (light: scores precomputed) =================
__global__ __launch_bounds__(256) void dag_reduce_kernel(
    const float* __restrict__ scores, const float* __restrict__ b2,
    const int* __restrict__ anc, const float* __restrict__ dmask,
    const float* __restrict__ E, float* __restrict__ dict)
{
    int warp = threadIdx.x >> 5, lane = threadIdx.x & 31;
    if (blockIdx.x == 0) dict[threadIdx.x] = 0.f;
    int c = blockIdx.x * 8 + warp;
    if (c >= C_) return;
    float p[8];
    float esum = 0.f;
    float b2v = b2[0];
    #pragma unroll
    for (int a = 0; a < 8; a++) {
        float mkk = dmask[c * 8 + a];
        float s = scores[c * 8 + a] + b2v + (1.f - mkk) * VERY_NEG;
        float e = __expf(s);
        esum += e;
        p[a] = e * mkk;
    }
    float inv = 1.f / esum;
    int nodes[8];
    #pragma unroll
    for (int a = 0; a < 8; a++) nodes[a] = anc[c * 8 + a];
    for (int t = lane; t < 256; t += 32) {
        float o = 0.f;
        #pragma unroll
        for (int a = 0; a < 8; a++) o += p[a] * E[(size_t)nodes[a] * 256 + t];
        dict[(size_t)(c + 1) * 256 + t] = o * inv;
    }
}

// ================= gather =================
__global__ __launch_bounds__(256) void gather_kernel(
    const int* __restrict__ ids, const float* __restrict__ Ein,
    const float* __restrict__ dict, float* __restrict__ xv, float* __restrict__ xd)
{
    int bs = blockIdx.x;
    int t = threadIdx.x;
    int id = ids[bs];
    size_t o = (size_t)bs * 256 + t;
    xv[o] = Ein[(size_t)id * 256 + t];
    xd[o] = dict[(size_t)id * 256 + t];
}

// ================= tensor-core attention: one block per (b,h) =================
// smem: Ks 256x36, Vt 32x260, Ps 256x36 (Q staging + P chunks), Ms 256
#define ATT_SMEM ((9216 + 8320 + 9216 + 256) * 4)
__global__ __launch_bounds__(256, 1) void attn_mma(
    const float* __restrict__ qkv, const float* __restrict__ code_mask, float* __restrict__ ctx)
{
    extern __shared__ float sm[];
    float* Ks = sm;
    float* Vt = sm + 9216;
    float* Ps = sm + 9216 + 8320;
    float* Ms = sm + 9216 + 8320 + 9216;
    int bh = blockIdx.x;
    int b = bh >> 3, h = bh & 7;
    int tid = threadIdx.x, lane = tid & 31, wid = tid >> 5;
    int tg = lane & 3, gp = lane >> 2;
    int w0 = wid * 32;
    const size_t qb = (size_t)b * 256 * 768 + h * 32;

    {
        int r = tid >> 3, c4 = tid & 7;
        #pragma unroll
        for (int i = 0; i < 8; i++) {
            int row = r + i * 32;
            float4 kv = *(const float4*)(qkv + qb + 256 + (size_t)row * 768 + c4 * 4);
            float4 qv = *(const float4*)(qkv + qb +       (size_t)row * 768 + c4 * 4);
            *(uint4*)&Ks[row * 36 + c4 * 4] = cvt4(kv);
            *(uint4*)&Ps[row * 36 + c4 * 4] = cvt4(qv);
        }
        int j = tid;
        #pragma unroll
        for (int d4 = 0; d4 < 8; d4++) {
            float4 vv = *(const float4*)(qkv + qb + 512 + (size_t)j * 768 + d4 * 4);
            uint4 vt = cvt4(vv);
            Vt[(d4 * 4 + 0) * 260 + j] = __uint_as_float(vt.x);
            Vt[(d4 * 4 + 1) * 260 + j] = __uint_as_float(vt.y);
            Vt[(d4 * 4 + 2) * 260 + j] = __uint_as_float(vt.z);
            Vt[(d4 * 4 + 3) * 260 + j] = __uint_as_float(vt.w);
        }
        Ms[tid] = (1.f - code_mask[b * 256 + tid]) * VERY_NEG;
    }
    __syncthreads();

    // Q fragments (rows w0..w0+31) into registers
    uint32_t qa[2][4][4];
    #pragma unroll
    for (int mi = 0; mi < 2; mi++)
        #pragma unroll
        for (int ks = 0; ks < 4; ks++) {
            int row = w0 + mi * 16 + gp;
            qa[mi][ks][0] = __float_as_uint(Ps[row * 36 + ks * 8 + tg]);
            qa[mi][ks][1] = __float_as_uint(Ps[(row + 8) * 36 + ks * 8 + tg]);
            qa[mi][ks][2] = __float_as_uint(Ps[row * 36 + ks * 8 + tg + 4]);
            qa[mi][ks][3] = __float_as_uint(Ps[(row + 8) * 36 + ks * 8 + tg + 4]);
        }

    float oacc[2][4][4];
    #pragma unroll
    for (int i = 0; i < 2; i++)
        #pragma unroll
        for (int j = 0; j < 4; j++)
            #pragma unroll
            for (int t = 0; t < 4; t++) oacc[i][j][t] = 0.f;
    float lr[4] = {0.f, 0.f, 0.f, 0.f};
    const float scale = 0.17677669529663687f;

    for (int jc = 0; jc < 8; jc++) {
        int j0 = jc * 32;
        float sacc[2][4][4];
        #pragma unroll
        for (int i = 0; i < 2; i++)
            #pragma unroll
            for (int j = 0; j < 4; j++)
                #pragma unroll
                for (int t = 0; t < 4; t++) sacc[i][j][t] = 0.f;
        #pragma unroll
        for (int ks = 0; ks < 4; ks++) {
            uint32_t bfr[4][2];
            #pragma unroll
            for (int ni = 0; ni < 4; ni++) {
                int nr = j0 + ni * 8 + gp;
                bfr[ni][0] = __float_as_uint(Ks[nr * 36 + ks * 8 + tg]);
                bfr[ni][1] = __float_as_uint(Ks[nr * 36 + ks * 8 + tg + 4]);
            }
            #pragma unroll
            for (int mi = 0; mi < 2; mi++)
                #pragma unroll
                for (int ni = 0; ni < 4; ni++)
                    mma_tf32(sacc[mi][ni], qa[mi][ks], bfr[ni]);
        }
        __syncwarp();
        #pragma unroll
        for (int mi = 0; mi < 2; mi++) {
            int row = w0 + mi * 16 + gp;
            #pragma unroll
            for (int ni = 0; ni < 4; ni++) {
                int colg = j0 + ni * 8 + 2 * tg;
                float m0 = Ms[colg], m1 = Ms[colg + 1];
                float e0 = __expf(sacc[mi][ni][0] * scale + m0);
                float e1 = __expf(sacc[mi][ni][1] * scale + m1);
                float e2 = __expf(sacc[mi][ni][2] * scale + m0);
                float e3 = __expf(sacc[mi][ni][3] * scale + m1);
                lr[mi * 2 + 0] += e0 + e1;
                lr[mi * 2 + 1] += e2 + e3;
                int cl = ni * 8 + 2 * tg;
                *(float2*)&Ps[row * 36 + cl] =
                    make_float2(__uint_as_float(f2tf(e0)), __uint_as_float(f2tf(e1)));
                *(float2*)&Ps[(row + 8) * 36 + cl] =
                    make_float2(__uint_as_float(f2tf(e2)), __uint_as_float(f2tf(e3)));
            }
        }
        __syncwarp();
        #pragma unroll
        for (int ks2 = 0; ks2 < 4; ks2++) {
            uint32_t pa[2][4], bvv[4][2];
            #pragma unroll
            for (int mi = 0; mi < 2; mi++) {
                int row = w0 + mi * 16 + gp;
                pa[mi][0] = __float_as_uint(Ps[row * 36 + ks2 * 8 + tg]);
                pa[mi][1] = __float_as_uint(Ps[(row + 8) * 36 + ks2 * 8 + tg]);
                pa[mi][2] = __float_as_uint(Ps[row * 36 + ks2 * 8 + tg + 4]);
                pa[mi][3] = __float_as_uint(Ps[(row + 8) * 36 + ks2 * 8 + tg + 4]);
            }
            #pragma unroll
            for (int ni = 0; ni < 4; ni++) {
                int d = ni * 8 + gp;
                bvv[ni][0] = __float_as_uint(Vt[d * 260 + j0 + ks2 * 8 + tg]);
                bvv[ni][1] = __float_as_uint(Vt[d * 260 + j0 + ks2 * 8 + tg + 4]);
            }
            #pragma unroll
            for (int mi = 0; mi < 2; mi++)
                #pragma unroll
                for (int ni = 0; ni < 4; ni++)
                    mma_tf32(oacc[mi][ni], pa[mi], bvv[ni]);
        }
        __syncwarp();
    }

    #pragma unroll
    for (int i = 0; i < 4; i++) {
        lr[i] += __shfl_xor_sync(0xffffffffu, lr[i], 1);
        lr[i] += __shfl_xor_sync(0xffffffffu, lr[i], 2);
    }
    #pragma unroll
    for (int mi = 0; mi < 2; mi++) {
        float inv0 = 1.f / lr[mi * 2 + 0];
        float inv1 = 1.f / lr[mi * 2 + 1];
        int row = w0 + mi * 16 + gp;
        #pragma unroll
        for (int ni = 0; ni < 4; ni++) {
            int col = h * 32 + ni * 8 + 2 * tg;
            *(float2*)(ctx + (size_t)(b * 256 + row) * 256 + col) =
                make_float2(oacc[mi][ni][0] * inv0, oacc[mi][ni][1] * inv0);
            *(float2*)(ctx + (size_t)(b * 256 + row + 8) * 256 + col) =
                make_float2(oacc[mi][ni][2] * inv1, oacc[mi][ni][3] * inv1);
        }
    }
}

// ================= pooling =================
__global__ __launch_bounds__(256) void pool_kernel(
    const float* __restrict__ x, const float* __restrict__ pw, const float* __restrict__ pb,
    const float* __restrict__ code_mask, float* __restrict__ out)
{
    __shared__ float sp[256], sq[256];
    int b = blockIdx.x;
    int j = threadIdx.x;
    const float* xr = x + ((size_t)b * 256 + j) * 256;
    float s = 0.f;
    for (int t = 0; t < 256; t++) s += xr[t] * pw[t];
    s += pb[0] + (1.f - code_mask[b * 256 + j]) * VERY_NEG;
    sq[j] = s;
    __syncthreads();
    for (int o = 128; o; o >>= 1) { if (j < o) sq[j] = fmaxf(sq[j], sq[j + o]); __syncthreads(); }
    float mx = sq[0];
    __syncthreads();
    float e = __expf(s - mx);
    sp[j] = e; sq[j] = e;
    __syncthreads();
    for (int o = 128; o; o >>= 1) { if (j < o) sq[j] += sq[j + o]; __syncthreads(); }
    float inv = 1.f / sq[0];
    __syncthreads();
    float o = 0.f;
    for (int t = 0; t < 256; t++) o += sp[t] * x[((size_t)b * 256 + t) * 256 + j];
    out[(size_t)b * 256 + j] = o * inv;
}

// ================= launch =================
extern "C" void kernel_launch(void* const* d_in, const int* in_sizes, int n_in,
                              void* d_out, int out_size)
{
    const int*   input_ids = (const int*)  d_in[0];
    const float* code_mask = (const float*)d_in[1];
    const int*   leaves    = (const int*)  d_in[2];
    const int*   anc       = (const int*)  d_in[3];
    const float* dmask     = (const float*)d_in[4];
    const float* Einit     = (const float*)d_in[5];
    const float* Einp      = (const float*)d_in[6];
    const float* aw1       = (const float*)d_in[7];
    const float* ab1       = (const float*)d_in[8];
    const float* aw2       = (const float*)d_in[9];
    const float* ab2       = (const float*)d_in[10];
    const float* pw        = (const float*)d_in[11];
    const float* pb        = (const float*)d_in[12];
    float* out = (float*)d_out;

    float *dict, *xv, *xd, *t1, *qkv, *ctx, *ff, *wT, *scores;
    cudaGetSymbolAddress((void**)&dict,   g_dict);
    cudaGetSymbolAddress((void**)&xv,     g_xv);
    cudaGetSymbolAddress((void**)&xd,     g_xd);
    cudaGetSymbolAddress((void**)&t1,     g_t1);
    cudaGetSymbolAddress((void**)&qkv,    g_qkv);
    cudaGetSymbolAddress((void**)&ctx,    g_ctx);
    cudaGetSymbolAddress((void**)&ff,     g_ff);
    cudaGetSymbolAddress((void**)&wT,     g_wT);
    cudaGetSymbolAddress((void**)&scores, g_scores);

    cudaFuncSetAttribute(tf32_gemm,    cudaFuncAttributeMaxDynamicSharedMemorySize, SM_TOTAL);
    cudaFuncSetAttribute(tf32_dag_mlp, cudaFuncAttributeMaxDynamicSharedMemorySize, SM_TOTAL);
    cudaFuncSetAttribute(attn_mma,     cudaFuncAttributeMaxDynamicSharedMemorySize, ATT_SMEM);

    // ---- batched weight transposes (one launch) ----
    TransArgs ta;
    ta.d[0] = {aw1, wT + 1572864, 512, 256};
    for (int l = 0; l < 2; l++) {
        int wb = 13 + 8 * l;
        float* base = wT + l * 786432;
        ta.d[1 + 6 * l + 0] = {(const float*)d_in[wb + 0], base + 0,      256, 256};
        ta.d[1 + 6 * l + 1] = {(const float*)d_in[wb + 1], base + 65536,  256, 256};
        ta.d[1 + 6 * l + 2] = {(const float*)d_in[wb + 2], base + 131072, 256, 256};
        ta.d[1 + 6 * l + 3] = {(const float*)d_in[wb + 3], base + 196608, 256, 256};
        ta.d[1 + 6 * l + 4] = {(const float*)d_in[wb + 4], base + 262144, 256, 1024};
        ta.d[1 + 6 * l + 5] = {(const float*)d_in[wb + 6], base + 524288, 1024, 256};
    }
    transpose_all<<<dim3(32, 32, 13), 256>>>(ta);
    zero_scores<<<(CA_ + 255) / 256, 256>>>(scores);

    // ---- DAG embedding pipeline ----
    tf32_dag_mlp<<<dim3(CA_ / 128, 2), 256, SM_TOTAL>>>(Einit, leaves, anc, dmask,
                                                        wT + 1572864, ab1, aw2, scores);
    dag_reduce_kernel<<<C_ / 8, 256>>>(scores, ab2, anc, dmask, Einit, dict);
    gather_kernel<<<BS_, 256>>>(input_ids, Einp, dict, xv, xd);

    // ---- two encoder layers ----
    auto encoder = [&](const float* X, int l, float* O) {
        float* base = wT + l * 786432;
        const float* fb1 = (const float*)d_in[13 + 8 * l + 5];
        const float* fb2 = (const float*)d_in[13 + 8 * l + 7];
        tf32_gemm<<<dim3(BS_ / 128, 6), 256, SM_TOTAL>>>(X, base + 0, nullptr, nullptr,
                                                         qkv, BS_, 768, 256, 0);
        attn_mma<<<B_ * 8, 256, ATT_SMEM>>>(qkv, code_mask, ctx);
        tf32_gemm<<<dim3(BS_ / 128, 2), 256, SM_TOTAL>>>(ctx, base + 196608, nullptr, X,
                                                         t1, BS_, 256, 256, 0);
        tf32_gemm<<<dim3(BS_ / 128, 8), 256, SM_TOTAL>>>(t1, base + 262144, fb1, nullptr,
                                                         ff, BS_, 1024, 256, 1);
        tf32_gemm<<<dim3(BS_ / 128, 2), 256, SM_TOTAL>>>(ff, base + 524288, fb2, t1,
                                                         O, BS_, 256, 1024, 0);
    };
    encoder(xv, 0, out);
    encoder(xd, 1, xv);

    pool_kernel<<<B_, 256>>>(xv, pw, pb, code_mask, out + (size_t)BS_ * H_);
}

// round 6
// speedup vs baseline: 3.6102x; 1.0920x over previous
#include <cuda_runtime.h>
#include <cstdint>
#include <cstddef>

#define VERY_NEG -1e30f
#define B_   128
#define S_   256
#define H_   256
#define C_   20000
#define A_   8
#define BS_  (B_*S_)      // 32768
#define CA_  (C_*A_)      // 160000

// ================= scratch =================
__device__ float g_dict[(C_+1)*H_];
__device__ float g_xv[BS_*H_];
__device__ float g_xd[BS_*H_];
__device__ float g_t1[BS_*H_];
__device__ float g_qkv[BS_*768];
__device__ float g_ctx[BS_*H_];
__device__ float g_ff[BS_*4*H_];
__device__ float g_wT[1703936 + 256];
__device__ float g_scores[CA_];

// ================= PTX helpers =================
__device__ __forceinline__ uint32_t smem_u32(const void* p) {
    uint32_t a;
    asm("{ .reg .u64 t; cvta.to.shared.u64 t, %1; cvt.u32.u64 %0, t; }" : "=r"(a) : "l"(p));
    return a;
}
__device__ __forceinline__ void mma_tf32(float* d, const uint32_t* a, const uint32_t* b)
{
    asm volatile(
        "mma.sync.aligned.m16n8k8.row.col.f32.tf32.tf32.f32 "
        "{%0,%1,%2,%3}, {%4,%5,%6,%7}, {%8,%9}, {%0,%1,%2,%3};\n"
        : "+f"(d[0]), "+f"(d[1]), "+f"(d[2]), "+f"(d[3])
        : "r"(a[0]), "r"(a[1]), "r"(a[2]), "r"(a[3]), "r"(b[0]), "r"(b[1]));
}
__device__ __forceinline__ void ldsm_x4(uint32_t* r, uint32_t addr)
{
    asm volatile("ldmatrix.sync.aligned.m8n8.x4.shared.b16 {%0,%1,%2,%3}, [%4];"
        : "=r"(r[0]), "=r"(r[1]), "=r"(r[2]), "=r"(r[3]) : "r"(addr));
}
__device__ __forceinline__ void ldsm_x2(uint32_t* r, uint32_t addr)
{
    asm volatile("ldmatrix.sync.aligned.m8n8.x2.shared.b16 {%0,%1}, [%2];"
        : "=r"(r[0]), "=r"(r[1]) : "r"(addr));
}
__device__ __forceinline__ uint32_t f2tf(float f)
{
    uint32_t u;
    asm("cvt.rna.tf32.f32 %0, %1;" : "=r"(u) : "f"(f));
    return u;
}
__device__ __forceinline__ uint4 cvt4(float4 v)
{
    uint4 o;
    o.x = f2tf(v.x); o.y = f2tf(v.y); o.z = f2tf(v.z); o.w = f2tf(v.w);
    return o;
}

#define SMSTRIDE 36
#define SM_TILE  (128 * SMSTRIDE)
#define SM_TOTAL (4 * SM_TILE * 4)

// one 128x128x32 block-step via LDSM fragment loads
__device__ __forceinline__ void mma_block(uint32_t sA, uint32_t sB,
                                          int wm, int wn, int lane, float acc[4][4][4])
{
    // A frag addr: row = tile_row + (lane&15), col4 = (lane>>4)*4
    uint32_t aoff = sA + (uint32_t)(((wm * 64 + (lane & 15)) * SMSTRIDE + (lane >> 4) * 4) * 4);
    // B frag addr (x2): row = tile_n + (lane&7), col4 = ((lane>>3)&1)*4
    uint32_t boff = sB + (uint32_t)(((wn * 32 + (lane & 7)) * SMSTRIDE + ((lane >> 3) & 1) * 4) * 4);
    #pragma unroll
    for (int ks = 0; ks < 4; ks++) {
        uint32_t a[4][4], b[4][2];
        #pragma unroll
        for (int mi = 0; mi < 4; mi++)
            ldsm_x4(a[mi], aoff + (uint32_t)((mi * 16 * SMSTRIDE + ks * 8) * 4));
        #pragma unroll
        for (int ni = 0; ni < 4; ni++)
            ldsm_x2(b[ni], boff + (uint32_t)((ni * 8 * SMSTRIDE + ks * 8) * 4));
        #pragma unroll
        for (int mi = 0; mi < 4; mi++)
            #pragma unroll
            for (int ni = 0; ni < 4; ni++)
                mma_tf32(acc[mi][ni], a[mi], b[ni]);
    }
}

// ================= dense tf32 GEMM: C[M,N] = op(A[M,K] @ Bt[N,K]^T) =================
__global__ __launch_bounds__(256) void tf32_gemm(
    const float* __restrict__ A, const float* __restrict__ Bt,
    const float* __restrict__ bias, const float* __restrict__ res,
    float* __restrict__ C, int M, int N, int K, int do_relu)
{
    extern __shared__ float sm[];
    uint32_t smb = smem_u32(sm);
    int tid = threadIdx.x;
    int bm = blockIdx.x, bn = blockIdx.y;
    int lane = tid & 31, wid = tid >> 5;
    int wm = wid >> 2, wn = wid & 3;
    int r0 = tid >> 3, c4 = tid & 7;

    const float* Ab = A + (size_t)(bm * 128 + r0) * K + c4 * 4;
    const float* Bb = Bt + (size_t)(bn * 128 + r0) * K + c4 * 4;
    float acc[4][4][4];
    #pragma unroll
    for (int i = 0; i < 4; i++)
        #pragma unroll
        for (int j = 0; j < 4; j++)
            #pragma unroll
            for (int t = 0; t < 4; t++) acc[i][j][t] = 0.f;

    int NC = K >> 5;
    float4 ra[4], rb[4];
    #pragma unroll
    for (int i = 0; i < 4; i++) {
        ra[i] = *(const float4*)(Ab + (size_t)i * 32 * K);
        rb[i] = *(const float4*)(Bb + (size_t)i * 32 * K);
    }
    #pragma unroll
    for (int i = 0; i < 4; i++) {
        *(uint4*)&sm[(r0 + i * 32) * SMSTRIDE + c4 * 4] = cvt4(ra[i]);
        *(uint4*)&sm[SM_TILE + (r0 + i * 32) * SMSTRIDE + c4 * 4] = cvt4(rb[i]);
    }
    __syncthreads();

    for (int kc = 0; kc < NC; kc++) {
        int buf = kc & 1;
        if (kc + 1 < NC) {
            int k0 = (kc + 1) << 5;
            #pragma unroll
            for (int i = 0; i < 4; i++) {
                ra[i] = *(const float4*)(Ab + (size_t)i * 32 * K + k0);
                rb[i] = *(const float4*)(Bb + (size_t)i * 32 * K + k0);
            }
        }
        mma_block(smb + (uint32_t)(buf * 2 * SM_TILE * 4),
                  smb + (uint32_t)((buf * 2 * SM_TILE + SM_TILE) * 4), wm, wn, lane, acc);
        if (kc + 1 < NC) {
            int nb = buf ^ 1;
            #pragma unroll
            for (int i = 0; i < 4; i++) {
                *(uint4*)&sm[nb * 2 * SM_TILE + (r0 + i * 32) * SMSTRIDE + c4 * 4] = cvt4(ra[i]);
                *(uint4*)&sm[nb * 2 * SM_TILE + SM_TILE + (r0 + i * 32) * SMSTRIDE + c4 * 4] = cvt4(rb[i]);
            }
            __syncthreads();
        }
    }

    int tg = lane & 3, gp = lane >> 2;
    #pragma unroll
    for (int mi = 0; mi < 4; mi++) {
        #pragma unroll
        for (int ni = 0; ni < 4; ni++) {
            int rl = wm * 64 + mi * 16 + gp;
            int col = bn * 128 + wn * 32 + ni * 8 + tg * 2;
            float2 bv = make_float2(0.f, 0.f);
            if (bias) bv = *(const float2*)(bias + col);
            #pragma unroll
            for (int h = 0; h < 2; h++) {
                size_t rowg = (size_t)bm * 128 + rl + h * 8;
                float2 v = make_float2(acc[mi][ni][2 * h] + bv.x, acc[mi][ni][2 * h + 1] + bv.y);
                if (res) {
                    float2 rv = *(const float2*)(res + rowg * N + col);
                    v.x += rv.x; v.y += rv.y;
                }
                if (do_relu) { v.x = fmaxf(v.x, 0.f); v.y = fmaxf(v.y, 0.f); }
                *(float2*)(C + rowg * N + col) = v;
            }
        }
    }
}

// ================= DAG MLP fused: accumulate relu(...)·w2 into scores =================
__global__ __launch_bounds__(256) void tf32_dag_mlp(
    const float* __restrict__ E, const int* __restrict__ leaves, const int* __restrict__ anc,
    const float* __restrict__ dmask, const float* __restrict__ w1T,
    const float* __restrict__ b1, const float* __restrict__ w2, float* __restrict__ scores)
{
    extern __shared__ float sm[];
    uint32_t smb = smem_u32(sm);
    int tid = threadIdx.x;
    int bm = blockIdx.x, bn = blockIdx.y;
    int lane = tid & 31, wid = tid >> 5;
    int wm = wid >> 2, wn = wid & 3;
    int r0 = tid >> 3, c4 = tid & 7;

    int nl[4], na[4];
    #pragma unroll
    for (int i = 0; i < 4; i++) {
        int m = bm * 128 + r0 + i * 32;
        nl[i] = leaves[m]; na[i] = anc[m];
    }
    const float* Bb = w1T + (size_t)(bn * 128 + r0) * 512 + c4 * 4;
    float acc[4][4][4];
    #pragma unroll
    for (int i = 0; i < 4; i++)
        #pragma unroll
        for (int j = 0; j < 4; j++)
            #pragma unroll
            for (int t = 0; t < 4; t++) acc[i][j][t] = 0.f;

    const int NC = 16;
    float4 ra[4], rb[4];
    #pragma unroll
    for (int i = 0; i < 4; i++) {
        ra[i] = *(const float4*)(E + (size_t)nl[i] * 256 + c4 * 4);
        rb[i] = *(const float4*)(Bb + (size_t)i * 32 * 512);
    }
    #pragma unroll
    for (int i = 0; i < 4; i++) {
        *(uint4*)&sm[(r0 + i * 32) * SMSTRIDE + c4 * 4] = cvt4(ra[i]);
        *(uint4*)&sm[SM_TILE + (r0 + i * 32) * SMSTRIDE + c4 * 4] = cvt4(rb[i]);
    }
    __syncthreads();

    for (int kc = 0; kc < NC; kc++) {
        int buf = kc & 1;
        if (kc + 1 < NC) {
            int k0 = (kc + 1) << 5;
            int kk = k0 & 255;
            bool first = k0 < 256;
            #pragma unroll
            for (int i = 0; i < 4; i++) {
                int node = first ? nl[i] : na[i];
                ra[i] = *(const float4*)(E + (size_t)node * 256 + kk + c4 * 4);
                rb[i] = *(const float4*)(Bb + (size_t)i * 32 * 512 + k0);
            }
        }
        mma_block(smb + (uint32_t)(buf * 2 * SM_TILE * 4),
                  smb + (uint32_t)((buf * 2 * SM_TILE + SM_TILE) * 4), wm, wn, lane, acc);
        if (kc + 1 < NC) {
            int nb = buf ^ 1;
            #pragma unroll
            for (int i = 0; i < 4; i++) {
                *(uint4*)&sm[nb * 2 * SM_TILE + (r0 + i * 32) * SMSTRIDE + c4 * 4] = cvt4(ra[i]);
                *(uint4*)&sm[nb * 2 * SM_TILE + SM_TILE + (r0 + i * 32) * SMSTRIDE + c4 * 4] = cvt4(rb[i]);
            }
            __syncthreads();
        }
    }

    int tg = lane & 3, gp = lane >> 2;
    float2 bv[4], w2v[4];
    #pragma unroll
    for (int ni = 0; ni < 4; ni++) {
        int col = bn * 128 + wn * 32 + ni * 8 + tg * 2;
        bv[ni] = *(const float2*)(b1 + col);
        w2v[ni] = *(const float2*)(w2 + col);
    }
    #pragma unroll
    for (int mi = 0; mi < 4; mi++) {
        int rl = wm * 64 + mi * 16 + gp;
        float mk0 = dmask[bm * 128 + rl];
        float mk1 = dmask[bm * 128 + rl + 8];
        float p0 = 0.f, p1 = 0.f;
        #pragma unroll
        for (int ni = 0; ni < 4; ni++) {
            float v0x = fmaxf(mk0 * acc[mi][ni][0] + bv[ni].x, 0.f);
            float v0y = fmaxf(mk0 * acc[mi][ni][1] + bv[ni].y, 0.f);
            float v1x = fmaxf(mk1 * acc[mi][ni][2] + bv[ni].x, 0.f);
            float v1y = fmaxf(mk1 * acc[mi][ni][3] + bv[ni].y, 0.f);
            p0 += v0x * w2v[ni].x + v0y * w2v[ni].y;
            p1 += v1x * w2v[ni].x + v1y * w2v[ni].y;
        }
        p0 += __shfl_xor_sync(0xffffffffu, p0, 1);
        p0 += __shfl_xor_sync(0xffffffffu, p0, 2);
        p1 += __shfl_xor_sync(0xffffffffu, p1, 1);
        p1 += __shfl_xor_sync(0xffffffffu, p1, 2);
        if (tg == 0) {
            atomicAdd(scores + bm * 128 + rl, p0);
            atomicAdd(scores + bm * 128 + rl + 8, p1);
        }
    }
}

// ================= zero scores =================
__global__ __launch_bounds__(256) void zero_scores(float* s)
{
    int i = blockIdx.x * 256 + threadIdx.x;
    if (i < CA_) s[i] = 0.f;
}

// ================= batched transpose =================
struct TransDesc { const float* src; float* dst; int R, C; };
struct TransArgs { TransDesc d[13]; };
__global__ __launch_bounds__(256) void transpose_all(TransArgs args)
{
    TransDesc t = args.d[blockIdx.z];
    if (blockIdx.x * 32 >= t.C || blockIdx.y * 32 >= t.R) return;
    __shared__ float tt[32][33];
    int x = threadIdx.x & 31, y0 = threadIdx.x >> 5;
    int c = blockIdx.x * 32 + x;
    #pragma unroll
    for (int i = 0; i < 32; i += 8)
        tt[y0 + i][x] = t.src[(size_t)(blockIdx.y * 32 + y0 + i) * t.C + c];
    __syncthreads();
    int rr = blockIdx.y * 32 + x;
    #pragma unroll
    for (int i = 0; i < 32; i += 8)
        t.dst[(size_t)(blockIdx.x * 32 + y0 + i) * t.R + rr] = tt[x][y0 + i];
}

// ================= DAG reduce =================
__global__ __launch_bounds__(256) void dag_reduce_kernel(
    const float* __restrict__ scores, const float* __restrict__ b2,
    const int* __restrict__ anc, const float* __restrict__ dmask,
    const float* __restrict__ E, float* __restrict__ dict)
{
    int warp = threadIdx.x >> 5, lane = threadIdx.x & 31;
    if (blockIdx.x == 0) dict[threadIdx.x] = 0.f;
    int c = blockIdx.x * 8 + warp;
    if (c >= C_) return;
    float p[8];
    float esum = 0.f;
    float b2v = b2[0];
    #pragma unroll
    for (int a = 0; a < 8; a++) {
        float mkk = dmask[c * 8 + a];
        float s = scores[c * 8 + a] + b2v + (1.f - mkk) * VERY_NEG;
        float e = __expf(s);
        esum += e;
        p[a] = e * mkk;
    }
    float inv = 1.f / esum;
    int nodes[8];
    #pragma unroll
    for (int a = 0; a < 8; a++) nodes[a] = anc[c * 8 + a];
    for (int t = lane; t < 256; t += 32) {
        float o = 0.f;
        #pragma unroll
        for (int a = 0; a < 8; a++) o += p[a] * E[(size_t)nodes[a] * 256 + t];
        dict[(size_t)(c + 1) * 256 + t] = o * inv;
    }
}

// ================= gather =================
__global__ __launch_bounds__(256) void gather_kernel(
    const int* __restrict__ ids, const float* __restrict__ Ein,
    const float* __restrict__ dict, float* __restrict__ xv, float* __restrict__ xd)
{
    int bs = blockIdx.x;
    int t = threadIdx.x;
    int id = ids[bs];
    size_t o = (size_t)bs * 256 + t;
    xv[o] = Ein[(size_t)id * 256 + t];
    xd[o] = dict[(size_t)id * 256 + t];
}

// ================= tensor-core attention (LDSM fragment loads) =================
#define ATT_SMEM ((9216 + 8320 + 9216 + 256) * 4)
__global__ __launch_bounds__(256, 1) void attn_mma(
    const float* __restrict__ qkv, const float* __restrict__ code_mask, float* __restrict__ ctx)
{
    extern __shared__ float sm[];
    uint32_t smb = smem_u32(sm);
    float* Ks = sm;
    float* Vt = sm + 9216;
    float* Ps = sm + 9216 + 8320;
    float* Ms = sm + 9216 + 8320 + 9216;
    int bh = blockIdx.x;
    int b = bh >> 3, h = bh & 7;
    int tid = threadIdx.x, lane = tid & 31, wid = tid >> 5;
    int tg = lane & 3, gp = lane >> 2;
    int w0 = wid * 32;
    const size_t qb = (size_t)b * 256 * 768 + h * 32;

    uint32_t aoffP = smb + (uint32_t)((9216 + 8320) * 4)
                   + (uint32_t)((((lane & 15)) * 36 + (lane >> 4) * 4) * 4);
    uint32_t boffK = smb + (uint32_t)((((lane & 7)) * 36 + ((lane >> 3) & 1) * 4) * 4);
    uint32_t boffV = smb + (uint32_t)(9216 * 4)
                   + (uint32_t)((((lane & 7)) * 260 + ((lane >> 3) & 1) * 4) * 4);

    {
        int r = tid >> 3, c4 = tid & 7;
        #pragma unroll
        for (int i = 0; i < 8; i++) {
            int row = r + i * 32;
            float4 kv = *(const float4*)(qkv + qb + 256 + (size_t)row * 768 + c4 * 4);
            float4 qv = *(const float4*)(qkv + qb +       (size_t)row * 768 + c4 * 4);
            *(uint4*)&Ks[row * 36 + c4 * 4] = cvt4(kv);
            *(uint4*)&Ps[row * 36 + c4 * 4] = cvt4(qv);
        }
        int j = tid;
        #pragma unroll
        for (int d4 = 0; d4 < 8; d4++) {
            float4 vv = *(const float4*)(qkv + qb + 512 + (size_t)j * 768 + d4 * 4);
            uint4 vt = cvt4(vv);
            Vt[(d4 * 4 + 0) * 260 + j] = __uint_as_float(vt.x);
            Vt[(d4 * 4 + 1) * 260 + j] = __uint_as_float(vt.y);
            Vt[(d4 * 4 + 2) * 260 + j] = __uint_as_float(vt.z);
            Vt[(d4 * 4 + 3) * 260 + j] = __uint_as_float(vt.w);
        }
        Ms[tid] = (1.f - code_mask[b * 256 + tid]) * VERY_NEG;
    }
    __syncthreads();

    uint32_t qa[2][4][4];
    #pragma unroll
    for (int mi = 0; mi < 2; mi++)
        #pragma unroll
        for (int ks = 0; ks < 4; ks++)
            ldsm_x4(qa[mi][ks], aoffP + (uint32_t)(((w0 + mi * 16) * 36 + ks * 8) * 4));

    float oacc[2][4][4];
    #pragma unroll
    for (int i = 0; i < 2; i++)
        #pragma unroll
        for (int j = 0; j < 4; j++)
            #pragma unroll
            for (int t = 0; t < 4; t++) oacc[i][j][t] = 0.f;
    float lr[4] = {0.f, 0.f, 0.f, 0.f};
    const float scale = 0.17677669529663687f;

    for (int jc = 0; jc < 8; jc++) {
        int j0 = jc * 32;
        float sacc[2][4][4];
        #pragma unroll
        for (int i = 0; i < 2; i++)
            #pragma unroll
            for (int j = 0; j < 4; j++)
                #pragma unroll
                for (int t = 0; t < 4; t++) sacc[i][j][t] = 0.f;
        #pragma unroll
        for (int ks = 0; ks < 4; ks++) {
            uint32_t bfr[4][2];
            #pragma unroll
            for (int ni = 0; ni < 4; ni++)
                ldsm_x2(bfr[ni], boffK + (uint32_t)(((j0 + ni * 8) * 36 + ks * 8) * 4));
            #pragma unroll
            for (int mi = 0; mi < 2; mi++)
                #pragma unroll
                for (int ni = 0; ni < 4; ni++)
                    mma_tf32(sacc[mi][ni], qa[mi][ks], bfr[ni]);
        }
        __syncwarp();
        #pragma unroll
        for (int mi = 0; mi < 2; mi++) {
            int row = w0 + mi * 16 + gp;
            #pragma unroll
            for (int ni = 0; ni < 4; ni++) {
                int colg = j0 + ni * 8 + 2 * tg;
                float m0 = Ms[colg], m1 = Ms[colg + 1];
                float e0 = __expf(sacc[mi][ni][0] * scale + m0);
                float e1 = __expf(sacc[mi][ni][1] * scale + m1);
                float e2 = __expf(sacc[mi][ni][2] * scale + m0);
                float e3 = __expf(sacc[mi][ni][3] * scale + m1);
                lr[mi * 2 + 0] += e0 + e1;
                lr[mi * 2 + 1] += e2 + e3;
                int cl = ni * 8 + 2 * tg;
                *(float2*)&Ps[row * 36 + cl] =
                    make_float2(__uint_as_float(f2tf(e0)), __uint_as_float(f2tf(e1)));
                *(float2*)&Ps[(row + 8) * 36 + cl] =
                    make_float2(__uint_as_float(f2tf(e2)), __uint_as_float(f2tf(e3)));
            }
        }
        __syncwarp();
        #pragma unroll
        for (int ks2 = 0; ks2 < 4; ks2++) {
            uint32_t pa[2][4], bvv[4][2];
            #pragma unroll
            for (int mi = 0; mi < 2; mi++)
                ldsm_x4(pa[mi], aoffP + (uint32_t)(((w0 + mi * 16) * 36 + ks2 * 8) * 4));
            #pragma unroll
            for (int ni = 0; ni < 4; ni++)
                ldsm_x2(bvv[ni], boffV + (uint32_t)(((ni * 8) * 260 + j0 + ks2 * 8) * 4));
            #pragma unroll
            for (int mi = 0; mi < 2; mi++)
                #pragma unroll
                for (int ni = 0; ni < 4; ni++)
                    mma_tf32(oacc[mi][ni], pa[mi], bvv[ni]);
        }
        __syncwarp();
    }

    #pragma unroll
    for (int i = 0; i < 4; i++) {
        lr[i] += __shfl_xor_sync(0xffffffffu, lr[i], 1);
        lr[i] += __shfl_xor_sync(0xffffffffu, lr[i], 2);
    }
    #pragma unroll
    for (int mi = 0; mi < 2; mi++) {
        float inv0 = 1.f / lr[mi * 2 + 0];
        float inv1 = 1.f / lr[mi * 2 + 1];
        int row = w0 + mi * 16 + gp;
        #pragma unroll
        for (int ni = 0; ni < 4; ni++) {
            int col = h * 32 + ni * 8 + 2 * tg;
            *(float2*)(ctx + (size_t)(b * 256 + row) * 256 + col) =
                make_float2(oacc[mi][ni][0] * inv0, oacc[mi][ni][1] * inv0);
            *(float2*)(ctx + (size_t)(b * 256 + row + 8) * 256 + col) =
                make_float2(oacc[mi][ni][2] * inv1, oacc[mi][ni][3] * inv1);
        }
    }
}

// ================= pooling =================
__global__ __launch_bounds__(256) void pool_kernel(
    const float* __restrict__ x, const float* __restrict__ pw, const float* __restrict__ pb,
    const float* __restrict__ code_mask, float* __restrict__ out)
{
    __shared__ float sp[256], sq[256];
    int b = blockIdx.x;
    int j = threadIdx.x;
    const float* xr = x + ((size_t)b * 256 + j) * 256;
    float s = 0.f;
    for (int t = 0; t < 256; t++) s += xr[t] * pw[t];
    s += pb[0] + (1.f - code_mask[b * 256 + j]) * VERY_NEG;
    sq[j] = s;
    __syncthreads();
    for (int o = 128; o; o >>= 1) { if (j < o) sq[j] = fmaxf(sq[j], sq[j + o]); __syncthreads(); }
    float mx = sq[0];
    __syncthreads();
    float e = __expf(s - mx);
    sp[j] = e; sq[j] = e;
    __syncthreads();
    for (int o = 128; o; o >>= 1) { if (j < o) sq[j] += sq[j + o]; __syncthreads(); }
    float inv = 1.f / sq[0];
    __syncthreads();
    float o = 0.f;
    for (int t = 0; t < 256; t++) o += sp[t] * x[((size_t)b * 256 + t) * 256 + j];
    out[(size_t)b * 256 + j] = o * inv;
}

// ================= launch =================
extern "C" void kernel_launch(void* const* d_in, const int* in_sizes, int n_in,
                              void* d_out, int out_size)
{
    const int*   input_ids = (const int*)  d_in[0];
    const float* code_mask = (const float*)d_in[1];
    const int*   leaves    = (const int*)  d_in[2];
    const int*   anc       = (const int*)  d_in[3];
    const float* dmask     = (const float*)d_in[4];
    const float* Einit     = (const float*)d_in[5];
    const float* Einp      = (const float*)d_in[6];
    const float* aw1       = (const float*)d_in[7];
    const float* ab1       = (const float*)d_in[8];
    const float* aw2       = (const float*)d_in[9];
    const float* ab2       = (const float*)d_in[10];
    const float* pw        = (const float*)d_in[11];
    const float* pb        = (const float*)d_in[12];
    float* out = (float*)d_out;

    float *dict, *xv, *xd, *t1, *qkv, *ctx, *ff, *wT, *scores;
    cudaGetSymbolAddress((void**)&dict,   g_dict);
    cudaGetSymbolAddress((void**)&xv,     g_xv);
    cudaGetSymbolAddress((void**)&xd,     g_xd);
    cudaGetSymbolAddress((void**)&t1,     g_t1);
    cudaGetSymbolAddress((void**)&qkv,    g_qkv);
    cudaGetSymbolAddress((void**)&ctx,    g_ctx);
    cudaGetSymbolAddress((void**)&ff,     g_ff);
    cudaGetSymbolAddress((void**)&wT,     g_wT);
    cudaGetSymbolAddress((void**)&scores, g_scores);

    cudaFuncSetAttribute(tf32_gemm,    cudaFuncAttributeMaxDynamicSharedMemorySize, SM_TOTAL);
    cudaFuncSetAttribute(tf32_dag_mlp, cudaFuncAttributeMaxDynamicSharedMemorySize, SM_TOTAL);
    cudaFuncSetAttribute(attn_mma,     cudaFuncAttributeMaxDynamicSharedMemorySize, ATT_SMEM);

    TransArgs ta;
    ta.d[0] = {aw1, wT + 1572864, 512, 256};
    for (int l = 0; l < 2; l++) {
        int wb = 13 + 8 * l;
        float* base = wT + l * 786432;
        ta.d[1 + 6 * l + 0] = {(const float*)d_in[wb + 0], base + 0,      256, 256};
        ta.d[1 + 6 * l + 1] = {(const float*)d_in[wb + 1], base + 65536,  256, 256};
        ta.d[1 + 6 * l + 2] = {(const float*)d_in[wb + 2], base + 131072, 256, 256};
        ta.d[1 + 6 * l + 3] = {(const float*)d_in[wb + 3], base + 196608, 256, 256};
        ta.d[1 + 6 * l + 4] = {(const float*)d_in[wb + 4], base + 262144, 256, 1024};
        ta.d[1 + 6 * l + 5] = {(const float*)d_in[wb + 6], base + 524288, 1024, 256};
    }
    transpose_all<<<dim3(32, 32, 13), 256>>>(ta);
    zero_scores<<<(CA_ + 255) / 256, 256>>>(scores);

    tf32_dag_mlp<<<dim3(CA_ / 128, 2), 256, SM_TOTAL>>>(Einit, leaves, anc, dmask,
                                                        wT + 1572864, ab1, aw2, scores);
    dag_reduce_kernel<<<C_ / 8, 256>>>(scores, ab2, anc, dmask, Einit, dict);
    gather_kernel<<<BS_, 256>>>(input_ids, Einp, dict, xv, xd);

    auto encoder = [&](const float* X, int l, float* O) {
        float* base = wT + l * 786432;
        const float* fb1 = (const float*)d_in[13 + 8 * l + 5];
        const float* fb2 = (const float*)d_in[13 + 8 * l + 7];
        tf32_gemm<<<dim3(BS_ / 128, 6), 256, SM_TOTAL>>>(X, base + 0, nullptr, nullptr,
                                                         qkv, BS_, 768, 256, 0);
        attn_mma<<<B_ * 8, 256, ATT_SMEM>>>(qkv, code_mask, ctx);
        tf32_gemm<<<dim3(BS_ / 128, 2), 256, SM_TOTAL>>>(ctx, base + 196608, nullptr, X,
                                                         t1, BS_, 256, 256, 0);
        tf32_gemm<<<dim3(BS_ / 128, 8), 256, SM_TOTAL>>>(t1, base + 262144, fb1, nullptr,
                                                         ff, BS_, 1024, 256, 1);
        tf32_gemm<<<dim3(BS_ / 128, 2), 256, SM_TOTAL>>>(ff, base + 524288, fb2, t1,
                                                         O, BS_, 256, 1024, 0);
    };
    encoder(xv, 0, out);
    encoder(xd, 1, xv);

    pool_kernel<<<B_, 256>>>(xv, pw, pb, code_mask, out + (size_t)BS_ * H_);
}

// round 10
// speedup vs baseline: 3.6617x; 1.0143x over previous
#include <cuda_runtime.h>
#include <cstdint>
#include <cstddef>

#define VERY_NEG -1e30f
#define B_   128
#define S_   256
#define H_   256
#define C_   20000
#define A_   8
#define BS_  (B_*S_)      // 32768
#define CA_  (C_*A_)      // 160000

// ================= scratch =================
__device__ float g_dict[(C_+1)*H_];
__device__ float g_xv[BS_*H_];
__device__ float g_xd[BS_*H_];
__device__ float g_t1[BS_*H_];
__device__ float g_qkv[BS_*768];
__device__ float g_ctx[BS_*H_];
__device__ float g_ff[BS_*4*H_];
__device__ float g_wT[1703936 + 256];   // tf32-RNA pre-rounded transposed weights
__device__ float g_scores[CA_];

// ================= PTX helpers =================
__device__ __forceinline__ uint32_t smem_u32(const void* p) {
    uint32_t a;
    asm("{ .reg .u64 t; cvta.to.shared.u64 t, %1; cvt.u32.u64 %0, t; }" : "=r"(a) : "l"(p));
    return a;
}
__device__ __forceinline__ void mma_tf32(float* d, const uint32_t* a, const uint32_t* b)
{
    asm volatile(
        "mma.sync.aligned.m16n8k8.row.col.f32.tf32.tf32.f32 "
        "{%0,%1,%2,%3}, {%4,%5,%6,%7}, {%8,%9}, {%0,%1,%2,%3};\n"
        : "+f"(d[0]), "+f"(d[1]), "+f"(d[2]), "+f"(d[3])
        : "r"(a[0]), "r"(a[1]), "r"(a[2]), "r"(a[3]), "r"(b[0]), "r"(b[1]));
}
__device__ __forceinline__ void ldsm_x4(uint32_t* r, uint32_t addr)
{
    asm volatile("ldmatrix.sync.aligned.m8n8.x4.shared.b16 {%0,%1,%2,%3}, [%4];"
        : "=r"(r[0]), "=r"(r[1]), "=r"(r[2]), "=r"(r[3]) : "r"(addr));
}
__device__ __forceinline__ void ldsm_x2(uint32_t* r, uint32_t addr)
{
    asm volatile("ldmatrix.sync.aligned.m8n8.x2.shared.b16 {%0,%1}, [%2];"
        : "=r"(r[0]), "=r"(r[1]) : "r"(addr));
}
__device__ __forceinline__ void cp16(uint32_t saddr, const void* gptr)
{
    asm volatile("cp.async.cg.shared.global [%0], [%1], 16;" :: "r"(saddr), "l"(gptr));
}
#define CP_COMMIT() asm volatile("cp.async.commit_group;" ::: "memory")
#define CP_WAIT(n)  asm volatile("cp.async.wait_group %0;" :: "n"(n) : "memory")
__device__ __forceinline__ uint32_t f2tf(float f)
{
    uint32_t u;
    asm("cvt.rna.tf32.f32 %0, %1;" : "=r"(u) : "f"(f));
    return u;
}
__device__ __forceinline__ uint4 cvt4(float4 v)
{
    uint4 o;
    o.x = f2tf(v.x); o.y = f2tf(v.y); o.z = f2tf(v.z); o.w = f2tf(v.w);
    return o;
}

#define SMSTRIDE 36
#define SM_TILE  (128 * SMSTRIDE)          // floats per tile
#define SM_TOTAL (4 * SM_TILE * 4)         // bytes: 2 bufs x (A+B)

// one 128x128x32 block-step via LDSM fragment loads
__device__ __forceinline__ void mma_block(uint32_t sA, uint32_t sB,
                                          int wm, int wn, int lane, float acc[4][4][4])
{
    uint32_t aoff = sA + (uint32_t)(((wm * 64 + (lane & 15)) * SMSTRIDE + (lane >> 4) * 4) * 4);
    uint32_t boff = sB + (uint32_t)(((wn * 32 + (lane & 7)) * SMSTRIDE + ((lane >> 3) & 1) * 4) * 4);
    #pragma unroll
    for (int ks = 0; ks < 4; ks++) {
        uint32_t a[4][4], b[4][2];
        #pragma unroll
        for (int mi = 0; mi < 4; mi++)
            ldsm_x4(a[mi], aoff + (uint32_t)((mi * 16 * SMSTRIDE + ks * 8) * 4));
        #pragma unroll
        for (int ni = 0; ni < 4; ni++)
            ldsm_x2(b[ni], boff + (uint32_t)((ni * 8 * SMSTRIDE + ks * 8) * 4));
        #pragma unroll
        for (int mi = 0; mi < 4; mi++)
            #pragma unroll
            for (int ni = 0; ni < 4; ni++)
                mma_tf32(acc[mi][ni], a[mi], b[ni]);
    }
}

// ================= dense tf32 GEMM: C[M,N] = op(A[M,K] @ Bt[N,K]^T) =================
// A staged via registers + cvt.rna; B (pre-rounded weights) staged via cp.async.
__global__ __launch_bounds__(256) void tf32_gemm(
    const float* __restrict__ A, const float* __restrict__ Bt,
    const float* __restrict__ bias, const float* __restrict__ res,
    float* __restrict__ C, int M, int N, int K, int do_relu)
{
    extern __shared__ float sm[];
    uint32_t smb = smem_u32(sm);
    int tid = threadIdx.x;
    int bm = blockIdx.x, bn = blockIdx.y;
    int lane = tid & 31, wid = tid >> 5;
    int wm = wid >> 2, wn = wid & 3;
    int r0 = tid >> 3, c4 = tid & 7;

    const float* Ab = A + (size_t)(bm * 128 + r0) * K + c4 * 4;
    const float* Bb = Bt + (size_t)(bn * 128 + r0) * K + c4 * 4;
    uint32_t soff = (uint32_t)((r0 * SMSTRIDE + c4 * 4) * 4);

    float acc[4][4][4];
    #pragma unroll
    for (int i = 0; i < 4; i++)
        #pragma unroll
        for (int j = 0; j < 4; j++)
            #pragma unroll
            for (int t = 0; t < 4; t++) acc[i][j][t] = 0.f;

    int NC = K >> 5;
    float4 ra[4];
    // prologue
    #pragma unroll
    for (int i = 0; i < 4; i++)
        cp16(smb + (uint32_t)(SM_TILE * 4) + soff + (uint32_t)(i * 32 * SMSTRIDE * 4),
             Bb + (size_t)i * 32 * K);
    CP_COMMIT();
    #pragma unroll
    for (int i = 0; i < 4; i++)
        ra[i] = *(const float4*)(Ab + (size_t)i * 32 * K);
    #pragma unroll
    for (int i = 0; i < 4; i++)
        *(uint4*)&sm[(r0 + i * 32) * SMSTRIDE + c4 * 4] = cvt4(ra[i]);
    CP_WAIT(0);
    __syncthreads();

    for (int kc = 0; kc < NC; kc++) {
        int buf = kc & 1;
        int nb = buf ^ 1;
        if (kc + 1 < NC) {
            int k0 = (kc + 1) << 5;
            #pragma unroll
            for (int i = 0; i < 4; i++)
                cp16(smb + (uint32_t)((nb * 2 * SM_TILE + SM_TILE) * 4) + soff
                         + (uint32_t)(i * 32 * SMSTRIDE * 4),
                     Bb + (size_t)i * 32 * K + k0);
            CP_COMMIT();
            #pragma unroll
            for (int i = 0; i < 4; i++)
                ra[i] = *(const float4*)(Ab + (size_t)i * 32 * K + k0);
        }
        mma_block(smb + (uint32_t)(buf * 2 * SM_TILE * 4),
                  smb + (uint32_t)((buf * 2 * SM_TILE + SM_TILE) * 4), wm, wn, lane, acc);
        if (kc + 1 < NC) {
            #pragma unroll
            for (int i = 0; i < 4; i++)
                *(uint4*)&sm[nb * 2 * SM_TILE + (r0 + i * 32) * SMSTRIDE + c4 * 4] = cvt4(ra[i]);
            CP_WAIT(0);
            __syncthreads();
        }
    }

    int tg = lane & 3, gp = lane >> 2;
    #pragma unroll
    for (int mi = 0; mi < 4; mi++) {
        #pragma unroll
        for (int ni = 0; ni < 4; ni++) {
            int rl = wm * 64 + mi * 16 + gp;
            int col = bn * 128 + wn * 32 + ni * 8 + tg * 2;
            float2 bv = make_float2(0.f, 0.f);
            if (bias) bv = *(const float2*)(bias + col);
            #pragma unroll
            for (int h = 0; h < 2; h++) {
                size_t rowg = (size_t)bm * 128 + rl + h * 8;
                float2 v = make_float2(acc[mi][ni][2 * h] + bv.x, acc[mi][ni][2 * h + 1] + bv.y);
                if (res) {
                    float2 rv = *(const float2*)(res + rowg * N + col);
                    v.x += rv.x; v.y += rv.y;
                }
                if (do_relu) { v.x = fmaxf(v.x, 0.f); v.y = fmaxf(v.y, 0.f); }
                *(float2*)(C + rowg * N + col) = v;
            }
        }
    }
}

// ================= DAG MLP fused: accumulate relu(...)·w2 into scores =================
__global__ __launch_bounds__(256) void tf32_dag_mlp(
    const float* __restrict__ E, const int* __restrict__ leaves, const int* __restrict__ anc,
    const float* __restrict__ dmask, const float* __restrict__ w1T,
    const float* __restrict__ b1, const float* __restrict__ w2, float* __restrict__ scores)
{
    extern __shared__ float sm[];
    uint32_t smb = smem_u32(sm);
    int tid = threadIdx.x;
    int bm = blockIdx.x, bn = blockIdx.y;
    int lane = tid & 31, wid = tid >> 5;
    int wm = wid >> 2, wn = wid & 3;
    int r0 = tid >> 3, c4 = tid & 7;

    int nl[4], na[4];
    #pragma unroll
    for (int i = 0; i < 4; i++) {
        int m = bm * 128 + r0 + i * 32;
        nl[i] = leaves[m]; na[i] = anc[m];
    }
    const float* Bb = w1T + (size_t)(bn * 128 + r0) * 512 + c4 * 4;
    uint32_t soff = (uint32_t)((r0 * SMSTRIDE + c4 * 4) * 4);

    float acc[4][4][4];
    #pragma unroll
    for (int i = 0; i < 4; i++)
        #pragma unroll
        for (int j = 0; j < 4; j++)
            #pragma unroll
            for (int t = 0; t < 4; t++) acc[i][j][t] = 0.f;

    const int NC = 16;
    float4 ra[4];
    #pragma unroll
    for (int i = 0; i < 4; i++)
        cp16(smb + (uint32_t)(SM_TILE * 4) + soff + (uint32_t)(i * 32 * SMSTRIDE * 4),
             Bb + (size_t)i * 32 * 512);
    CP_COMMIT();
    #pragma unroll
    for (int i = 0; i < 4; i++)
        ra[i] = *(const float4*)(E + (size_t)nl[i] * 256 + c4 * 4);
    #pragma unroll
    for (int i = 0; i < 4; i++)
        *(uint4*)&sm[(r0 + i * 32) * SMSTRIDE + c4 * 4] = cvt4(ra[i]);
    CP_WAIT(0);
    __syncthreads();

    for (int kc = 0; kc < NC; kc++) {
        int buf = kc & 1;
        int nb = buf ^ 1;
        if (kc + 1 < NC) {
            int k0 = (kc + 1) << 5;
            int kk = k0 & 255;
            bool first = k0 < 256;
            #pragma unroll
            for (int i = 0; i < 4; i++)
                cp16(smb + (uint32_t)((nb * 2 * SM_TILE + SM_TILE) * 4) + soff
                         + (uint32_t)(i * 32 * SMSTRIDE * 4),
                     Bb + (size_t)i * 32 * 512 + k0);
            CP_COMMIT();
            #pragma unroll
            for (int i = 0; i < 4; i++) {
                int node = first ? nl[i] : na[i];
                ra[i] = *(const float4*)(E + (size_t)node * 256 + kk + c4 * 4);
            }
        }
        mma_block(smb + (uint32_t)(buf * 2 * SM_TILE * 4),
                  smb + (uint32_t)((buf * 2 * SM_TILE + SM_TILE) * 4), wm, wn, lane, acc);
        if (kc + 1 < NC) {
            #pragma unroll
            for (int i = 0; i < 4; i++)
                *(uint4*)&sm[nb * 2 * SM_TILE + (r0 + i * 32) * SMSTRIDE + c4 * 4] = cvt4(ra[i]);
            CP_WAIT(0);
            __syncthreads();
        }
    }

    int tg = lane & 3, gp = lane >> 2;
    float2 bv[4], w2v[4];
    #pragma unroll
    for (int ni = 0; ni < 4; ni++) {
        int col = bn * 128 + wn * 32 + ni * 8 + tg * 2;
        bv[ni] = *(const float2*)(b1 + col);
        w2v[ni] = *(const float2*)(w2 + col);
    }
    #pragma unroll
    for (int mi = 0; mi < 4; mi++) {
        int rl = wm * 64 + mi * 16 + gp;
        float mk0 = dmask[bm * 128 + rl];
        float mk1 = dmask[bm * 128 + rl + 8];
        float p0 = 0.f, p1 = 0.f;
        #pragma unroll
        for (int ni = 0; ni < 4; ni++) {
            float v0x = fmaxf(mk0 * acc[mi][ni][0] + bv[ni].x, 0.f);
            float v0y = fmaxf(mk0 * acc[mi][ni][1] + bv[ni].y, 0.f);
            float v1x = fmaxf(mk1 * acc[mi][ni][2] + bv[ni].x, 0.f);
            float v1y = fmaxf(mk1 * acc[mi][ni][3] + bv[ni].y, 0.f);
            p0 += v0x * w2v[ni].x + v0y * w2v[ni].y;
            p1 += v1x * w2v[ni].x + v1y * w2v[ni].y;
        }
        p0 += __shfl_xor_sync(0xffffffffu, p0, 1);
        p0 += __shfl_xor_sync(0xffffffffu, p0, 2);
        p1 += __shfl_xor_sync(0xffffffffu, p1, 1);
        p1 += __shfl_xor_sync(0xffffffffu, p1, 2);
        if (tg == 0) {
            atomicAdd(scores + bm * 128 + rl, p0);
            atomicAdd(scores + bm * 128 + rl + 8, p1);
        }
    }
}

// ================= zero scores =================
__global__ __launch_bounds__(256) void zero_scores(float* s)
{
    int i = blockIdx.x * 256 + threadIdx.x;
    if (i < CA_) s[i] = 0.f;
}

// ================= batched transpose (stores tf32-RNA-rounded weights) =================
struct TransDesc { const float* src; float* dst; int R, C; };
struct TransArgs { TransDesc d[13]; };
__global__ __launch_bounds__(256) void transpose_all(TransArgs args)
{
    TransDesc t = args.d[blockIdx.z];
    if (blockIdx.x * 32 >= t.C || blockIdx.y * 32 >= t.R) return;
    __shared__ float tt[32][33];
    int x = threadIdx.x & 31, y0 = threadIdx.x >> 5;
    int c = blockIdx.x * 32 + x;
    #pragma unroll
    for (int i = 0; i < 32; i += 8)
        tt[y0 + i][x] = t.src[(size_t)(blockIdx.y * 32 + y0 + i) * t.C + c];
    __syncthreads();
    int rr = blockIdx.y * 32 + x;
    #pragma unroll
    for (int i = 0; i < 32; i += 8)
        t.dst[(size_t)(blockIdx.x * 32 + y0 + i) * t.R + rr] =
            __uint_as_float(f2tf(tt[x][y0 + i]));
}

// ================= DAG reduce =================
__global__ __launch_bounds__(256) void dag_reduce_kernel(
    const float* __restrict__ scores, const float* __restrict__ b2,
    const int* __restrict__ anc, const float* __restrict__ dmask,
    const float* __restrict__ E, float* __restrict__ dict)
{
    int warp = threadIdx.x >> 5, lane = threadIdx.x & 31;
    if (blockIdx.x == 0) dict[threadIdx.x] = 0.f;
    int c = blockIdx.x * 8 + warp;
    if (c >= C_) return;
    float p[8];
    float esum = 0.f;
    float b2v = b2[0];
    #pragma unroll
    for (int a = 0; a < 8; a++) {
        float mkk = dmask[c * 8 + a];
        float s = scores[c * 8 + a] + b2v + (1.f - mkk) * VERY_NEG;
        float e = __expf(s);
        esum += e;
        p[a] = e * mkk;
    }
    float inv = 1.f / esum;
    int nodes[8];
    #pragma unroll
    for (int a = 0; a < 8; a++) nodes[a] = anc[c * 8 + a];
    for (int t = lane; t < 256; t += 32) {
        float o = 0.f;
        #pragma unroll
        for (int a = 0; a < 8; a++) o += p[a] * E[(size_t)nodes[a] * 256 + t];
        dict[(size_t)(c + 1) * 256 + t] = o * inv;
    }
}

// ================= gather =================
__global__ __launch_bounds__(256) void gather_kernel(
    const int* __restrict__ ids, const float* __restrict__ Ein,
    const float* __restrict__ dict, float* __restrict__ xv, float* __restrict__ xd)
{
    int bs = blockIdx.x;
    int t = threadIdx.x;
    int id = ids[bs];
    size_t o = (size_t)bs * 256 + t;
    xv[o] = Ein[(size_t)id * 256 + t];
    xd[o] = dict[(size_t)id * 256 + t];
}

// ================= tensor-core attention (LDSM fragment loads) =================
#define ATT_SMEM ((9216 + 8320 + 9216 + 256) * 4)
__global__ __launch_bounds__(256, 1) void attn_mma(
    const float* __restrict__ qkv, const float* __restrict__ code_mask, float* __restrict__ ctx)
{
    extern __shared__ float sm[];
    uint32_t smb = smem_u32(sm);
    float* Ks = sm;
    float* Vt = sm + 9216;
    float* Ps = sm + 9216 + 8320;
    float* Ms = sm + 9216 + 8320 + 9216;
    int bh = blockIdx.x;
    int b = bh >> 3, h = bh & 7;
    int tid = threadIdx.x, lane = tid & 31, wid = tid >> 5;
    int tg = lane & 3, gp = lane >> 2;
    int w0 = wid * 32;
    const size_t qb = (size_t)b * 256 * 768 + h * 32;

    uint32_t aoffP = smb + (uint32_t)((9216 + 8320) * 4)
                   + (uint32_t)((((lane & 15)) * 36 + (lane >> 4) * 4) * 4);
    uint32_t boffK = smb + (uint32_t)((((lane & 7)) * 36 + ((lane >> 3) & 1) * 4) * 4);
    uint32_t boffV = smb + (uint32_t)(9216 * 4)
                   + (uint32_t)((((lane & 7)) * 260 + ((lane >> 3) & 1) * 4) * 4);

    {
        int r = tid >> 3, c4 = tid & 7;
        #pragma unroll
        for (int i = 0; i < 8; i++) {
            int row = r + i * 32;
            float4 kv = *(const float4*)(qkv + qb + 256 + (size_t)row * 768 + c4 * 4);
            float4 qv = *(const float4*)(qkv + qb +       (size_t)row * 768 + c4 * 4);
            *(uint4*)&Ks[row * 36 + c4 * 4] = cvt4(kv);
            *(uint4*)&Ps[row * 36 + c4 * 4] = cvt4(qv);
        }
        int j = tid;
        #pragma unroll
        for (int d4 = 0; d4 < 8; d4++) {
            float4 vv = *(const float4*)(qkv + qb + 512 + (size_t)j * 768 + d4 * 4);
            uint4 vt = cvt4(vv);
            Vt[(d4 * 4 + 0) * 260 + j] = __uint_as_float(vt.x);
            Vt[(d4 * 4 + 1) * 260 + j] = __uint_as_float(vt.y);
            Vt[(d4 * 4 + 2) * 260 + j] = __uint_as_float(vt.z);
            Vt[(d4 * 4 + 3) * 260 + j] = __uint_as_float(vt.w);
        }
        Ms[tid] = (1.f - code_mask[b * 256 + tid]) * VERY_NEG;
    }
    __syncthreads();

    uint32_t qa[2][4][4];
    #pragma unroll
    for (int mi = 0; mi < 2; mi++)
        #pragma unroll
        for (int ks = 0; ks < 4; ks++)
            ldsm_x4(qa[mi][ks], aoffP + (uint32_t)(((w0 + mi * 16) * 36 + ks * 8) * 4));

    float oacc[2][4][4];
    #pragma unroll
    for (int i = 0; i < 2; i++)
        #pragma unroll
        for (int j = 0; j < 4; j++)
            #pragma unroll
            for (int t = 0; t < 4; t++) oacc[i][j][t] = 0.f;
    float lr[4] = {0.f, 0.f, 0.f, 0.f};
    const float scale = 0.17677669529663687f;

    for (int jc = 0; jc < 8; jc++) {
        int j0 = jc * 32;
        float sacc[2][4][4];
        #pragma unroll
        for (int i = 0; i < 2; i++)
            #pragma unroll
            for (int j = 0; j < 4; j++)
                #pragma unroll
                for (int t = 0; t < 4; t++) sacc[i][j][t] = 0.f;
        #pragma unroll
        for (int ks = 0; ks < 4; ks++) {
            uint32_t bfr[4][2];
            #pragma unroll
            for (int ni = 0; ni < 4; ni++)
                ldsm_x2(bfr[ni], boffK + (uint32_t)(((j0 + ni * 8) * 36 + ks * 8) * 4));
            #pragma unroll
            for (int mi = 0; mi < 2; mi++)
                #pragma unroll
                for (int ni = 0; ni < 4; ni++)
                    mma_tf32(sacc[mi][ni], qa[mi][ks], bfr[ni]);
        }
        __syncwarp();
        #pragma unroll
        for (int mi = 0; mi < 2; mi++) {
            int row = w0 + mi * 16 + gp;
            #pragma unroll
            for (int ni = 0; ni < 4; ni++) {
                int colg = j0 + ni * 8 + 2 * tg;
                float m0 = Ms[colg], m1 = Ms[colg + 1];
                float e0 = __expf(sacc[mi][ni][0] * scale + m0);
                float e1 = __expf(sacc[mi][ni][1] * scale + m1);
                float e2 = __expf(sacc[mi][ni][2] * scale + m0);
                float e3 = __expf(sacc[mi][ni][3] * scale + m1);
                lr[mi * 2 + 0] += e0 + e1;
                lr[mi * 2 + 1] += e2 + e3;
                int cl = ni * 8 + 2 * tg;
                *(float2*)&Ps[row * 36 + cl] =
                    make_float2(__uint_as_float(f2tf(e0)), __uint_as_float(f2tf(e1)));
                *(float2*)&Ps[(row + 8) * 36 + cl] =
                    make_float2(__uint_as_float(f2tf(e2)), __uint_as_float(f2tf(e3)));
            }
        }
        __syncwarp();
        #pragma unroll
        for (int ks2 = 0; ks2 < 4; ks2++) {
            uint32_t pa[2][4], bvv[4][2];
            #pragma unroll
            for (int mi = 0; mi < 2; mi++)
                ldsm_x4(pa[mi], aoffP + (uint32_t)(((w0 + mi * 16) * 36 + ks2 * 8) * 4));
            #pragma unroll
            for (int ni = 0; ni < 4; ni++)
                ldsm_x2(bvv[ni], boffV + (uint32_t)(((ni * 8) * 260 + j0 + ks2 * 8) * 4));
            #pragma unroll
            for (int mi = 0; mi < 2; mi++)
                #pragma unroll
                for (int ni = 0; ni < 4; ni++)
                    mma_tf32(oacc[mi][ni], pa[mi], bvv[ni]);
        }
        __syncwarp();
    }

    #pragma unroll
    for (int i = 0; i < 4; i++) {
        lr[i] += __shfl_xor_sync(0xffffffffu, lr[i], 1);
        lr[i] += __shfl_xor_sync(0xffffffffu, lr[i], 2);
    }
    #pragma unroll
    for (int mi = 0; mi < 2; mi++) {
        float inv0 = 1.f / lr[mi * 2 + 0];
        float inv1 = 1.f / lr[mi * 2 + 1];
        int row = w0 + mi * 16 + gp;
        #pragma unroll
        for (int ni = 0; ni < 4; ni++) {
            int col = h * 32 + ni * 8 + 2 * tg;
            *(float2*)(ctx + (size_t)(b * 256 + row) * 256 + col) =
                make_float2(oacc[mi][ni][0] * inv0, oacc[mi][ni][1] * inv0);
            *(float2*)(ctx + (size_t)(b * 256 + row + 8) * 256 + col) =
                make_float2(oacc[mi][ni][2] * inv1, oacc[mi][ni][3] * inv1);
        }
    }
}

// ================= pooling =================
__global__ __launch_bounds__(256) void pool_kernel(
    const float* __restrict__ x, const float* __restrict__ pw, const float* __restrict__ pb,
    const float* __restrict__ code_mask, float* __restrict__ out)
{
    __shared__ float sp[256], sq[256];
    int b = blockIdx.x;
    int j = threadIdx.x;
    const float* xr = x + ((size_t)b * 256 + j) * 256;
    float s = 0.f;
    for (int t = 0; t < 256; t++) s += xr[t] * pw[t];
    s += pb[0] + (1.f - code_mask[b * 256 + j]) * VERY_NEG;
    sq[j] = s;
    __syncthreads();
    for (int o = 128; o; o >>= 1) { if (j < o) sq[j] = fmaxf(sq[j], sq[j + o]); __syncthreads(); }
    float mx = sq[0];
    __syncthreads();
    float e = __expf(s - mx);
    sp[j] = e; sq[j] = e;
    __syncthreads();
    for (int o = 128; o; o >>= 1) { if (j < o) sq[j] += sq[j + o]; __syncthreads(); }
    float inv = 1.f / sq[0];
    __syncthreads();
    float o = 0.f;
    for (int t = 0; t < 256; t++) o += sp[t] * x[((size_t)b * 256 + t) * 256 + j];
    out[(size_t)b * 256 + j] = o * inv;
}

// ================= launch =================
extern "C" void kernel_launch(void* const* d_in, const int* in_sizes, int n_in,
                              void* d_out, int out_size)
{
    const int*   input_ids = (const int*)  d_in[0];
    const float* code_mask = (const float*)d_in[1];
    const int*   leaves    = (const int*)  d_in[2];
    const int*   anc       = (const int*)  d_in[3];
    const float* dmask     = (const float*)d_in[4];
    const float* Einit     = (const float*)d_in[5];
    const float* Einp      = (const float*)d_in[6];
    const float* aw1       = (const float*)d_in[7];
    const float* ab1       = (const float*)d_in[8];
    const float* aw2       = (const float*)d_in[9];
    const float* ab2       = (const float*)d_in[10];
    const float* pw        = (const float*)d_in[11];
    const float* pb        = (const float*)d_in[12];
    float* out = (float*)d_out;

    float *dict, *xv, *xd, *t1, *qkv, *ctx, *ff, *wT, *scores;
    cudaGetSymbolAddress((void**)&dict,   g_dict);
    cudaGetSymbolAddress((void**)&xv,     g_xv);
    cudaGetSymbolAddress((void**)&xd,     g_xd);
    cudaGetSymbolAddress((void**)&t1,     g_t1);
    cudaGetSymbolAddress((void**)&qkv,    g_qkv);
    cudaGetSymbolAddress((void**)&ctx,    g_ctx);
    cudaGetSymbolAddress((void**)&ff,     g_ff);
    cudaGetSymbolAddress((void**)&wT,     g_wT);
    cudaGetSymbolAddress((void**)&scores, g_scores);

    cudaFuncSetAttribute(tf32_gemm,    cudaFuncAttributeMaxDynamicSharedMemorySize, SM_TOTAL);
    cudaFuncSetAttribute(tf32_dag_mlp, cudaFuncAttributeMaxDynamicSharedMemorySize, SM_TOTAL);
    cudaFuncSetAttribute(attn_mma,     cudaFuncAttributeMaxDynamicSharedMemorySize, ATT_SMEM);

    TransArgs ta;
    ta.d[0] = {aw1, wT + 1572864, 512, 256};
    for (int l = 0; l < 2; l++) {
        int wb = 13 + 8 * l;
        float* base = wT + l * 786432;
        ta.d[1 + 6 * l + 0] = {(const float*)d_in[wb + 0], base + 0,      256, 256};
        ta.d[1 + 6 * l + 1] = {(const float*)d_in[wb + 1], base + 65536,  256, 256};
        ta.d[1 + 6 * l + 2] = {(const float*)d_in[wb + 2], base + 131072, 256, 256};
        ta.d[1 + 6 * l + 3] = {(const float*)d_in[wb + 3], base + 196608, 256, 256};
        ta.d[1 + 6 * l + 4] = {(const float*)d_in[wb + 4], base + 262144, 256, 1024};
        ta.d[1 + 6 * l + 5] = {(const float*)d_in[wb + 6], base + 524288, 1024, 256};
    }
    transpose_all<<<dim3(32, 32, 13), 256>>>(ta);
    zero_scores<<<(CA_ + 255) / 256, 256>>>(scores);

    tf32_dag_mlp<<<dim3(CA_ / 128, 2), 256, SM_TOTAL>>>(Einit, leaves, anc, dmask,
                                                        wT + 1572864, ab1, aw2, scores);
    dag_reduce_kernel<<<C_ / 8, 256>>>(scores, ab2, anc, dmask, Einit, dict);
    gather_kernel<<<BS_, 256>>>(input_ids, Einp, dict, xv, xd);

    auto encoder = [&](const float* X, int l, float* O) {
        float* base = wT + l * 786432;
        const float* fb1 = (const float*)d_in[13 + 8 * l + 5];
        const float* fb2 = (const float*)d_in[13 + 8 * l + 7];
        tf32_gemm<<<dim3(BS_ / 128, 6), 256, SM_TOTAL>>>(X, base + 0, nullptr, nullptr,
                                                         qkv, BS_, 768, 256, 0);
        attn_mma<<<B_ * 8, 256, ATT_SMEM>>>(qkv, code_mask, ctx);
        tf32_gemm<<<dim3(BS_ / 128, 2), 256, SM_TOTAL>>>(ctx, base + 196608, nullptr, X,
                                                         t1, BS_, 256, 256, 0);
        tf32_gemm<<<dim3(BS_ / 128, 8), 256, SM_TOTAL>>>(t1, base + 262144, fb1, nullptr,
                                                         ff, BS_, 1024, 256, 1);
        tf32_gemm<<<dim3(BS_ / 128, 2), 256, SM_TOTAL>>>(ff, base + 524288, fb2, t1,
                                                         O, BS_, 256, 1024, 0);
    };
    encoder(xv, 0, out);
    encoder(xd, 1, xv);

    pool_kernel<<<B_, 256>>>(xv, pw, pb, code_mask, out + (size_t)BS_ * H_);
}